// round 2
// baseline (speedup 1.0000x reference)
#include <cuda_runtime.h>
#include <math.h>

// Problem constants
#define B_    4
#define S_    2048
#define DIN   512
#define DK    2048
#define DV    64
#define MTOT  (B_*S_)        // 8192

// ---------------- scratch (static device globals: allocation-free) ----------
__device__ float g_Q[(size_t)MTOT * DK];     // 64 MB
__device__ float g_K[(size_t)MTOT * DK];     // 64 MB
__device__ float g_V[(size_t)MTOT * DV];     //  2 MB
__device__ float g_P[(size_t)B_ * S_ * S_];  // 64 MB  (scores -> probs in place)

// ============================================================================
// Generic batched NN SGEMM: C[M,N] = A[M,K] * B[K,N], all row-major.
// 128x128 tile, BK=8, 256 threads, 8x8 per-thread microtile, float4 I/O.
// N may be < 128 (guarded); M, K must be multiples of 128 / 8 (they are).
// If causal_kcap != 0, the K loop is capped at (m0 + 128): used for P*V where
// P[q,k] == 0 for k > q (softmax zero-fills the masked half).
// ============================================================================
__global__ __launch_bounds__(256)
void sgemm_nn(const float* __restrict__ A, const float* __restrict__ Bm,
              float* __restrict__ C,
              int M, int N, int K, int lda, int ldb, int ldc,
              long sA, long sB, long sC, int causal_kcap)
{
    __shared__ __align__(16) float As[8][128];
    __shared__ __align__(16) float Bs[8][128];

    const int bz = blockIdx.z;
    A  += (size_t)bz * sA;
    Bm += (size_t)bz * sB;
    C  += (size_t)bz * sC;

    const int m0 = blockIdx.y * 128;
    const int n0 = blockIdx.x * 128;
    const int tid = threadIdx.x;
    const int tx = tid & 15, ty = tid >> 4;

    int Keff = K;
    if (causal_kcap) Keff = (m0 + 128 < K) ? (m0 + 128) : K;

    // A tile: 128 rows x 8 k-cols; each thread loads one float4
    const int arow = tid >> 1;
    const int acol = (tid & 1) * 4;
    // B tile: 8 k-rows x 128 cols
    const int brow = tid >> 5;
    const int bcol = (tid & 31) * 4;
    const bool bok = (n0 + bcol) < N;   // N multiple of 4 => float4 fully in/out

    float acc[8][8];
#pragma unroll
    for (int i = 0; i < 8; i++)
#pragma unroll
        for (int j = 0; j < 8; j++) acc[i][j] = 0.f;

    for (int kt = 0; kt < Keff; kt += 8) {
        float4 av = *(const float4*)(A + (size_t)(m0 + arow) * lda + kt + acol);
        As[acol + 0][arow] = av.x;
        As[acol + 1][arow] = av.y;
        As[acol + 2][arow] = av.z;
        As[acol + 3][arow] = av.w;

        float4 bv = make_float4(0.f, 0.f, 0.f, 0.f);
        if (bok) bv = *(const float4*)(Bm + (size_t)(kt + brow) * ldb + n0 + bcol);
        *(float4*)&Bs[brow][bcol] = bv;

        __syncthreads();
#pragma unroll
        for (int k = 0; k < 8; k++) {
            float4 a0 = *(const float4*)&As[k][ty * 8];
            float4 a1 = *(const float4*)&As[k][ty * 8 + 4];
            float4 b0 = *(const float4*)&Bs[k][tx * 8];
            float4 b1 = *(const float4*)&Bs[k][tx * 8 + 4];
            float a[8] = {a0.x, a0.y, a0.z, a0.w, a1.x, a1.y, a1.z, a1.w};
            float b[8] = {b0.x, b0.y, b0.z, b0.w, b1.x, b1.y, b1.z, b1.w};
#pragma unroll
            for (int i = 0; i < 8; i++)
#pragma unroll
                for (int j = 0; j < 8; j++)
                    acc[i][j] = fmaf(a[i], b[j], acc[i][j]);
        }
        __syncthreads();
    }

#pragma unroll
    for (int i = 0; i < 8; i++) {
        const int m = m0 + ty * 8 + i;
        const int n = n0 + tx * 8;
        if (n < N)
            *(float4*)(C + (size_t)m * ldc + n) =
                make_float4(acc[i][0], acc[i][1], acc[i][2], acc[i][3]);
        if (n + 4 < N)
            *(float4*)(C + (size_t)m * ldc + n + 4) =
                make_float4(acc[i][4], acc[i][5], acc[i][6], acc[i][7]);
    }
}

// ============================================================================
// Scores: P[b,q,k] = scale * sum_d Q[b,q,d]*K[b,k,d]   (NT GEMM, causal skip)
// Tiles fully above the diagonal are skipped entirely; softmax never reads k>q.
// ============================================================================
__global__ __launch_bounds__(256)
void scores_nt(const float* __restrict__ Qg, const float* __restrict__ Kg,
               float* __restrict__ Pg, float scale)
{
    const int bz = blockIdx.z;
    const int q0 = blockIdx.y * 128;
    const int k0 = blockIdx.x * 128;
    if (k0 > q0 + 127) return;   // entire tile masked by causality

    const float* A  = Qg + (size_t)bz * S_ * DK;
    const float* Bm = Kg + (size_t)bz * S_ * DK;
    float*       C  = Pg + (size_t)bz * S_ * S_;

    __shared__ __align__(16) float As[8][128];
    __shared__ __align__(16) float Bs[8][128];

    const int tid = threadIdx.x;
    const int tx = tid & 15, ty = tid >> 4;
    const int lrow = tid >> 1;         // 0..127
    const int lcol = (tid & 1) * 4;    // 0 or 4

    float acc[8][8];
#pragma unroll
    for (int i = 0; i < 8; i++)
#pragma unroll
        for (int j = 0; j < 8; j++) acc[i][j] = 0.f;

    for (int dt = 0; dt < DK; dt += 8) {
        float4 av = *(const float4*)(A + (size_t)(q0 + lrow) * DK + dt + lcol);
        As[lcol + 0][lrow] = av.x;
        As[lcol + 1][lrow] = av.y;
        As[lcol + 2][lrow] = av.z;
        As[lcol + 3][lrow] = av.w;

        float4 bv = *(const float4*)(Bm + (size_t)(k0 + lrow) * DK + dt + lcol);
        Bs[lcol + 0][lrow] = bv.x;
        Bs[lcol + 1][lrow] = bv.y;
        Bs[lcol + 2][lrow] = bv.z;
        Bs[lcol + 3][lrow] = bv.w;

        __syncthreads();
#pragma unroll
        for (int k = 0; k < 8; k++) {
            float4 a0 = *(const float4*)&As[k][ty * 8];
            float4 a1 = *(const float4*)&As[k][ty * 8 + 4];
            float4 b0 = *(const float4*)&Bs[k][tx * 8];
            float4 b1 = *(const float4*)&Bs[k][tx * 8 + 4];
            float a[8] = {a0.x, a0.y, a0.z, a0.w, a1.x, a1.y, a1.z, a1.w};
            float b[8] = {b0.x, b0.y, b0.z, b0.w, b1.x, b1.y, b1.z, b1.w};
#pragma unroll
            for (int i = 0; i < 8; i++)
#pragma unroll
                for (int j = 0; j < 8; j++)
                    acc[i][j] = fmaf(a[i], b[j], acc[i][j]);
        }
        __syncthreads();
    }

#pragma unroll
    for (int i = 0; i < 8; i++) {
        const int q = q0 + ty * 8 + i;
        const int k = k0 + tx * 8;
        *(float4*)(C + (size_t)q * S_ + k) =
            make_float4(acc[i][0] * scale, acc[i][1] * scale,
                        acc[i][2] * scale, acc[i][3] * scale);
        *(float4*)(C + (size_t)q * S_ + k + 4) =
            make_float4(acc[i][4] * scale, acc[i][5] * scale,
                        acc[i][6] * scale, acc[i][7] * scale);
    }
}

// ============================================================================
// Causal row softmax in place: reads k in [0,q], writes probs; zeroes k in (q,S)
// so the following P*V GEMM needs no masking. One block (256 thr) per row.
// ============================================================================
__global__ __launch_bounds__(256)
void softmax_causal(float* __restrict__ P)
{
    const int row = blockIdx.x;          // b*S + q
    const int q = row & (S_ - 1);
    float* p = P + (size_t)row * S_;
    const int tid = threadIdx.x;

    __shared__ float sm[8];
    __shared__ float bval;

    // ---- pass 1: row max over [0, q] ----
    float mx = -INFINITY;
    for (int k = tid; k <= q; k += 256) mx = fmaxf(mx, p[k]);
#pragma unroll
    for (int o = 16; o; o >>= 1) mx = fmaxf(mx, __shfl_xor_sync(0xffffffffu, mx, o));
    if ((tid & 31) == 0) sm[tid >> 5] = mx;
    __syncthreads();
    if (tid < 32) {
        float v = (tid < 8) ? sm[tid] : -INFINITY;
#pragma unroll
        for (int o = 4; o; o >>= 1) v = fmaxf(v, __shfl_xor_sync(0xffffffffu, v, o));
        if (tid == 0) bval = v;
    }
    __syncthreads();
    mx = bval;

    // ---- pass 2: exp + sum (stores exp in place) ----
    float s = 0.f;
    for (int k = tid; k <= q; k += 256) {
        float e = expf(p[k] - mx);
        p[k] = e;
        s += e;
    }
#pragma unroll
    for (int o = 16; o; o >>= 1) s += __shfl_xor_sync(0xffffffffu, s, o);
    __syncthreads();                     // protect sm reuse
    if ((tid & 31) == 0) sm[tid >> 5] = s;
    __syncthreads();
    if (tid < 32) {
        float v = (tid < 8) ? sm[tid] : 0.f;
#pragma unroll
        for (int o = 4; o; o >>= 1) v += __shfl_xor_sync(0xffffffffu, v, o);
        if (tid == 0) bval = v;
    }
    __syncthreads();
    const float inv = 1.f / bval;

    // ---- pass 3: normalize valid region, zero masked region ----
    for (int k = tid; k <= q; k += 256) p[k] *= inv;
    for (int k = q + 1 + tid; k < S_; k += 256) p[k] = 0.f;
}

// ============================================================================
// Host launcher — graph-capturable: kernel launches only, no sync, no alloc.
// ============================================================================
extern "C" void kernel_launch(void* const* d_in, const int* in_sizes, int n_in,
                              void* d_out, int out_size)
{
    const float* x  = (const float*)d_in[0];   // [B,S,DIN]
    const float* Wq = (const float*)d_in[1];   // [DIN,DK]
    const float* Wk = (const float*)d_in[2];   // [DIN,DK]
    const float* Wv = (const float*)d_in[3];   // [DIN,DV]
    float* out = (float*)d_out;                // [B,S,DV]

    float *Qp, *Kp, *Vp, *Pp;
    cudaGetSymbolAddress((void**)&Qp, g_Q);
    cudaGetSymbolAddress((void**)&Kp, g_K);
    cudaGetSymbolAddress((void**)&Vp, g_V);
    cudaGetSymbolAddress((void**)&Pp, g_P);

    const dim3 blk(256);
    const float scale = 1.0f / sqrtf((float)DK);

    // QKV projections (x is [MTOT, DIN])
    sgemm_nn<<<dim3(DK / 128, MTOT / 128, 1), blk>>>(
        x, Wq, Qp, MTOT, DK, DIN, DIN, DK, DK, 0, 0, 0, 0);
    sgemm_nn<<<dim3(DK / 128, MTOT / 128, 1), blk>>>(
        x, Wk, Kp, MTOT, DK, DIN, DIN, DK, DK, 0, 0, 0, 0);
    sgemm_nn<<<dim3(1, MTOT / 128, 1), blk>>>(
        x, Wv, Vp, MTOT, DV, DIN, DIN, DV, DV, 0, 0, 0, 0);

    // Scores with causal tile-skip + scale
    scores_nt<<<dim3(S_ / 128, S_ / 128, B_), blk>>>(Qp, Kp, Pp, scale);

    // Row softmax (causal, zero-fills masked half)
    softmax_causal<<<dim3(B_ * S_), blk>>>(Pp);

    // O = P @ V  (batched over B; K capped at diagonal since P is causal-zeroed)
    sgemm_nn<<<dim3(1, S_ / 128, B_), blk>>>(
        Pp, Vp, out, S_, DV, S_, S_, DV, DV,
        (long)S_ * S_, (long)S_ * DV, (long)S_ * DV, 1);
}

// round 6
// speedup vs baseline: 3.4067x; 3.4067x over previous
#include <cuda_runtime.h>
#include <cuda_bf16.h>
#include <math.h>
#include <stdint.h>

// Problem constants
#define B_    4
#define S_    2048
#define DIN   512
#define DK    2048
#define DV    64
#define MTOT  (B_*S_)        // 8192

// ---------------- scratch (static device globals: allocation-free) ----------
__device__ __nv_bfloat16 g_xh[(size_t)MTOT * DIN];
__device__ __nv_bfloat16 g_xl[(size_t)MTOT * DIN];
__device__ __nv_bfloat16 g_Wqt_h[(size_t)DK * DIN];   // [N=DK][K=DIN]
__device__ __nv_bfloat16 g_Wqt_l[(size_t)DK * DIN];
__device__ __nv_bfloat16 g_Wkt_h[(size_t)DK * DIN];
__device__ __nv_bfloat16 g_Wkt_l[(size_t)DK * DIN];
__device__ __nv_bfloat16 g_Qh[(size_t)MTOT * DK];
__device__ __nv_bfloat16 g_Ql[(size_t)MTOT * DK];
__device__ __nv_bfloat16 g_Kh[(size_t)MTOT * DK];
__device__ __nv_bfloat16 g_Kl[(size_t)MTOT * DK];
__device__ float         g_V [(size_t)MTOT * DV];
__device__ __nv_bfloat16 g_Vt_h[(size_t)B_ * DV * S_];  // [b][DV][S]
__device__ __nv_bfloat16 g_Vt_l[(size_t)B_ * DV * S_];
__device__ float         g_P [(size_t)B_ * S_ * S_];    // fp32 scores
__device__ __nv_bfloat16 g_Ph[(size_t)B_ * S_ * S_];    // softmax probs hi/lo
__device__ __nv_bfloat16 g_Pl[(size_t)B_ * S_ * S_];

// ---------------------------------------------------------------------------
// PTX helpers
// ---------------------------------------------------------------------------
__device__ __forceinline__ void ldsm_x4(uint32_t& r0, uint32_t& r1, uint32_t& r2,
                                        uint32_t& r3, uint32_t addr) {
    asm volatile("ldmatrix.sync.aligned.m8n8.x4.shared.b16 {%0,%1,%2,%3}, [%4];\n"
                 : "=r"(r0), "=r"(r1), "=r"(r2), "=r"(r3) : "r"(addr));
}
__device__ __forceinline__ void mma_bf16(float* c, uint32_t a0, uint32_t a1,
                                         uint32_t a2, uint32_t a3,
                                         uint32_t b0, uint32_t b1) {
    asm volatile("mma.sync.aligned.m16n8k16.row.col.f32.bf16.bf16.f32 "
                 "{%0,%1,%2,%3}, {%4,%5,%6,%7}, {%8,%9}, {%0,%1,%2,%3};\n"
                 : "+f"(c[0]), "+f"(c[1]), "+f"(c[2]), "+f"(c[3])
                 : "r"(a0), "r"(a1), "r"(a2), "r"(a3), "r"(b0), "r"(b1));
}

// ---------------------------------------------------------------------------
// Elementwise split: fp32 -> (hi bf16, lo bf16)
// ---------------------------------------------------------------------------
__global__ __launch_bounds__(256)
void split_kernel(const float* __restrict__ src, __nv_bfloat16* __restrict__ h,
                  __nv_bfloat16* __restrict__ l, int n)
{
    int i = blockIdx.x * 256 + threadIdx.x;
    if (i < n) {
        float v = src[i];
        __nv_bfloat16 hv = __float2bfloat16(v);
        h[i] = hv;
        l[i] = __float2bfloat16(v - __bfloat162float(hv));
    }
}

// ---------------------------------------------------------------------------
// Split + transpose: src fp32 [R,C] (row-major) -> dst hi/lo bf16 [C,R].
// R, C multiples of 32. Batched via grid.z with strides.
// ---------------------------------------------------------------------------
__global__ __launch_bounds__(256)
void split_transpose(const float* __restrict__ src, __nv_bfloat16* __restrict__ dh,
                     __nv_bfloat16* __restrict__ dl, int R, int C,
                     long sSrc, long sDst)
{
    __shared__ float t[32][33];
    const int b = blockIdx.z;
    src += (size_t)b * sSrc;
    dh  += (size_t)b * sDst;
    dl  += (size_t)b * sDst;
    const int c0 = blockIdx.x * 32;
    const int r0 = blockIdx.y * 32;
    const int x = threadIdx.x, y = threadIdx.y;   // block (32, 8)
#pragma unroll
    for (int i = 0; i < 32; i += 8)
        t[y + i][x] = src[(size_t)(r0 + y + i) * C + c0 + x];
    __syncthreads();
#pragma unroll
    for (int i = 0; i < 32; i += 8) {
        float v = t[x][y + i];
        __nv_bfloat16 hv = __float2bfloat16(v);
        size_t o = (size_t)(c0 + y + i) * R + r0 + x;
        dh[o] = hv;
        dl[o] = __float2bfloat16(v - __bfloat162float(hv));
    }
}

// ---------------------------------------------------------------------------
// bf16 split-NT tensor-core GEMM:
//   C[M,N] = (Ah+Al)[M,K] * (Bh+Bl)[N,K]^T   (drops Al*Bl)
// 128x128x32 tile, 256 threads (8 warps, 4x2), ldmatrix + mma.m16n8k16.
// mode 0: write fp32 alpha*C;  mode 1: write (Ch, Cl) bf16 split.
// causal 1: skip tile if n0 > m0+127 (scores);  causal 2: K capped at m0+128.
// ---------------------------------------------------------------------------
#define LDS 40   // smem row stride in bf16 elems (80B: conflict-free ldmatrix)

__global__ __launch_bounds__(256)
void gemm_bf16split_nt(const __nv_bfloat16* __restrict__ Ah_g,
                       const __nv_bfloat16* __restrict__ Al_g,
                       const __nv_bfloat16* __restrict__ Bh_g,
                       const __nv_bfloat16* __restrict__ Bl_g,
                       float* __restrict__ Cf,
                       __nv_bfloat16* __restrict__ Ch,
                       __nv_bfloat16* __restrict__ Cl,
                       int M, int N, int K, int lda, int ldb, int ldc,
                       long sA, long sB, long sC,
                       float alpha, int mode, int causal)
{
    __shared__ __nv_bfloat16 sAh[128][LDS], sAl[128][LDS];
    __shared__ __nv_bfloat16 sBh[128][LDS], sBl[128][LDS];

    const int m0 = blockIdx.y * 128;
    const int n0 = blockIdx.x * 128;
    if (causal == 1 && n0 > m0 + 127) return;

    const int bz = blockIdx.z;
    Ah_g += (size_t)bz * sA;  Al_g += (size_t)bz * sA;
    Bh_g += (size_t)bz * sB;  Bl_g += (size_t)bz * sB;

    int Keff = K;
    if (causal == 2) Keff = (m0 + 128 < K) ? (m0 + 128) : K;

    const int tid  = threadIdx.x;
    const int lane = tid & 31;
    const int wid  = tid >> 5;
    const int wm   = wid >> 1;      // 0..3
    const int wn   = wid & 1;       // 0..1

    const uint32_t uAh = (uint32_t)__cvta_generic_to_shared(&sAh[0][0]);
    const uint32_t uAl = (uint32_t)__cvta_generic_to_shared(&sAl[0][0]);
    const uint32_t uBh = (uint32_t)__cvta_generic_to_shared(&sBh[0][0]);
    const uint32_t uBl = (uint32_t)__cvta_generic_to_shared(&sBl[0][0]);

    float acc[2][8][4];
#pragma unroll
    for (int i = 0; i < 2; i++)
#pragma unroll
        for (int j = 0; j < 8; j++)
#pragma unroll
            for (int q = 0; q < 4; q++) acc[i][j][q] = 0.f;

    // global->smem vector load coords (uint4 = 8 bf16; 4 vecs per 32-elem row)
    const int v0row = tid >> 2;
    const int v0col = (tid & 3) << 3;
    const int v1row = (tid + 256) >> 2;
    const int v1col = ((tid + 256) & 3) << 3;

    const uint4 zero4 = make_uint4(0, 0, 0, 0);

    for (int kt = 0; kt < Keff; kt += 32) {
        // A tiles
        *(uint4*)&sAh[v0row][v0col] =
            *(const uint4*)(Ah_g + (size_t)(m0 + v0row) * lda + kt + v0col);
        *(uint4*)&sAh[v1row][v1col] =
            *(const uint4*)(Ah_g + (size_t)(m0 + v1row) * lda + kt + v1col);
        *(uint4*)&sAl[v0row][v0col] =
            *(const uint4*)(Al_g + (size_t)(m0 + v0row) * lda + kt + v0col);
        *(uint4*)&sAl[v1row][v1col] =
            *(const uint4*)(Al_g + (size_t)(m0 + v1row) * lda + kt + v1col);
        // B tiles (rows are n; guard n < N, zero-fill otherwise)
        *(uint4*)&sBh[v0row][v0col] = (n0 + v0row < N)
            ? *(const uint4*)(Bh_g + (size_t)(n0 + v0row) * ldb + kt + v0col) : zero4;
        *(uint4*)&sBh[v1row][v1col] = (n0 + v1row < N)
            ? *(const uint4*)(Bh_g + (size_t)(n0 + v1row) * ldb + kt + v1col) : zero4;
        *(uint4*)&sBl[v0row][v0col] = (n0 + v0row < N)
            ? *(const uint4*)(Bl_g + (size_t)(n0 + v0row) * ldb + kt + v0col) : zero4;
        *(uint4*)&sBl[v1row][v1col] = (n0 + v1row < N)
            ? *(const uint4*)(Bl_g + (size_t)(n0 + v1row) * ldb + kt + v1col) : zero4;

        __syncthreads();

#pragma unroll
        for (int ks = 0; ks < 32; ks += 16) {
            // A fragments (2 m-tiles, hi+lo)
            const int arow = wm * 32 + (lane & 15);
            const int acol = ks + ((lane >> 4) << 3);
            uint32_t ah[2][4], al[2][4];
            ldsm_x4(ah[0][0], ah[0][1], ah[0][2], ah[0][3],
                    uAh + (uint32_t)((arow) * LDS + acol) * 2);
            ldsm_x4(ah[1][0], ah[1][1], ah[1][2], ah[1][3],
                    uAh + (uint32_t)((arow + 16) * LDS + acol) * 2);
            ldsm_x4(al[0][0], al[0][1], al[0][2], al[0][3],
                    uAl + (uint32_t)((arow) * LDS + acol) * 2);
            ldsm_x4(al[1][0], al[1][1], al[1][2], al[1][3],
                    uAl + (uint32_t)((arow + 16) * LDS + acol) * 2);

            const int brow = wn * 64 + (lane & 7) + ((lane >> 4) << 3);
            const int bcol = ks + (((lane >> 3) & 1) << 3);
#pragma unroll
            for (int p = 0; p < 4; p++) {
                uint32_t bh[4], bl[4];
                ldsm_x4(bh[0], bh[1], bh[2], bh[3],
                        uBh + (uint32_t)((brow + 16 * p) * LDS + bcol) * 2);
                ldsm_x4(bl[0], bl[1], bl[2], bl[3],
                        uBl + (uint32_t)((brow + 16 * p) * LDS + bcol) * 2);
#pragma unroll
                for (int mt = 0; mt < 2; mt++) {
                    // n-tile 2p
                    mma_bf16(acc[mt][2*p],   ah[mt][0], ah[mt][1], ah[mt][2], ah[mt][3], bh[0], bh[1]);
                    mma_bf16(acc[mt][2*p],   ah[mt][0], ah[mt][1], ah[mt][2], ah[mt][3], bl[0], bl[1]);
                    mma_bf16(acc[mt][2*p],   al[mt][0], al[mt][1], al[mt][2], al[mt][3], bh[0], bh[1]);
                    // n-tile 2p+1
                    mma_bf16(acc[mt][2*p+1], ah[mt][0], ah[mt][1], ah[mt][2], ah[mt][3], bh[2], bh[3]);
                    mma_bf16(acc[mt][2*p+1], ah[mt][0], ah[mt][1], ah[mt][2], ah[mt][3], bl[2], bl[3]);
                    mma_bf16(acc[mt][2*p+1], al[mt][0], al[mt][1], al[mt][2], al[mt][3], bh[2], bh[3]);
                }
            }
        }
        __syncthreads();
    }

    // ------------------- epilogue -------------------
    const int r = lane >> 2;
    const int c = (lane & 3) * 2;
#pragma unroll
    for (int mt = 0; mt < 2; mt++) {
#pragma unroll
        for (int nt = 0; nt < 8; nt++) {
            const int gm = m0 + wm * 32 + mt * 16 + r;
            const int gn = n0 + wn * 64 + nt * 8 + c;
            const float* a = acc[mt][nt];
            if (mode == 0) {
                float* Cb = Cf + (size_t)bz * sC;
                if (gn < N) {
                    Cb[(size_t)gm * ldc + gn]           = a[0] * alpha;
                    Cb[(size_t)gm * ldc + gn + 1]       = a[1] * alpha;
                    Cb[(size_t)(gm + 8) * ldc + gn]     = a[2] * alpha;
                    Cb[(size_t)(gm + 8) * ldc + gn + 1] = a[3] * alpha;
                }
            } else {
                if (gn < N) {
#pragma unroll
                    for (int e = 0; e < 4; e++) {
                        const int mm = gm + (e >> 1) * 8;
                        const int nn = gn + (e & 1);
                        float v = a[e];
                        __nv_bfloat16 hv = __float2bfloat16(v);
                        Ch[(size_t)mm * ldc + nn] = hv;
                        Cl[(size_t)mm * ldc + nn] =
                            __float2bfloat16(v - __bfloat162float(hv));
                    }
                }
            }
        }
    }
}

// ============================================================================
// fp32 SIMT SGEMM (kept only for the tiny V projection, N=64, K=512)
// ============================================================================
__global__ __launch_bounds__(256)
void sgemm_nn(const float* __restrict__ A, const float* __restrict__ Bm,
              float* __restrict__ C,
              int M, int N, int K, int lda, int ldb, int ldc)
{
    __shared__ __align__(16) float As[8][128];
    __shared__ __align__(16) float Bs[8][128];

    const int m0 = blockIdx.y * 128;
    const int n0 = blockIdx.x * 128;
    const int tid = threadIdx.x;
    const int tx = tid & 15, ty = tid >> 4;

    const int arow = tid >> 1;
    const int acol = (tid & 1) * 4;
    const int brow = tid >> 5;
    const int bcol = (tid & 31) * 4;
    const bool bok = (n0 + bcol) < N;

    float acc[8][8];
#pragma unroll
    for (int i = 0; i < 8; i++)
#pragma unroll
        for (int j = 0; j < 8; j++) acc[i][j] = 0.f;

    for (int kt = 0; kt < K; kt += 8) {
        float4 av = *(const float4*)(A + (size_t)(m0 + arow) * lda + kt + acol);
        As[acol + 0][arow] = av.x;
        As[acol + 1][arow] = av.y;
        As[acol + 2][arow] = av.z;
        As[acol + 3][arow] = av.w;
        float4 bv = make_float4(0.f, 0.f, 0.f, 0.f);
        if (bok) bv = *(const float4*)(Bm + (size_t)(kt + brow) * ldb + n0 + bcol);
        *(float4*)&Bs[brow][bcol] = bv;
        __syncthreads();
#pragma unroll
        for (int k = 0; k < 8; k++) {
            float4 a0 = *(const float4*)&As[k][ty * 8];
            float4 a1 = *(const float4*)&As[k][ty * 8 + 4];
            float4 b0 = *(const float4*)&Bs[k][tx * 8];
            float4 b1 = *(const float4*)&Bs[k][tx * 8 + 4];
            float a[8] = {a0.x, a0.y, a0.z, a0.w, a1.x, a1.y, a1.z, a1.w};
            float b[8] = {b0.x, b0.y, b0.z, b0.w, b1.x, b1.y, b1.z, b1.w};
#pragma unroll
            for (int i = 0; i < 8; i++)
#pragma unroll
                for (int j = 0; j < 8; j++)
                    acc[i][j] = fmaf(a[i], b[j], acc[i][j]);
        }
        __syncthreads();
    }
#pragma unroll
    for (int i = 0; i < 8; i++) {
        const int m = m0 + ty * 8 + i;
        const int n = n0 + tx * 8;
        if (n < N)
            *(float4*)(C + (size_t)m * ldc + n) =
                make_float4(acc[i][0], acc[i][1], acc[i][2], acc[i][3]);
        if (n + 4 < N)
            *(float4*)(C + (size_t)m * ldc + n + 4) =
                make_float4(acc[i][4], acc[i][5], acc[i][6], acc[i][7]);
    }
}

// ============================================================================
// Causal row softmax: reads fp32 scores k in [0,q]; writes bf16 hi/lo probs,
// zero-fills k in (q, S). One 256-thread block per row.
// ============================================================================
__global__ __launch_bounds__(256)
void softmax_causal(const float* __restrict__ P,
                    __nv_bfloat16* __restrict__ Ph,
                    __nv_bfloat16* __restrict__ Pl,
                    float* __restrict__ Pexp)
{
    const int row = blockIdx.x;          // b*S + q
    const int q = row & (S_ - 1);
    const float* p = P + (size_t)row * S_;
    float* pe = Pexp + (size_t)row * S_;
    __nv_bfloat16* ph = Ph + (size_t)row * S_;
    __nv_bfloat16* pl = Pl + (size_t)row * S_;
    const int tid = threadIdx.x;

    __shared__ float sm[8];
    __shared__ float bval;

    float mx = -INFINITY;
    for (int k = tid; k <= q; k += 256) mx = fmaxf(mx, p[k]);
#pragma unroll
    for (int o = 16; o; o >>= 1) mx = fmaxf(mx, __shfl_xor_sync(0xffffffffu, mx, o));
    if ((tid & 31) == 0) sm[tid >> 5] = mx;
    __syncthreads();
    if (tid < 32) {
        float v = (tid < 8) ? sm[tid] : -INFINITY;
#pragma unroll
        for (int o = 4; o; o >>= 1) v = fmaxf(v, __shfl_xor_sync(0xffffffffu, v, o));
        if (tid == 0) bval = v;
    }
    __syncthreads();
    mx = bval;

    float s = 0.f;
    for (int k = tid; k <= q; k += 256) {
        float e = expf(p[k] - mx);
        pe[k] = e;
        s += e;
    }
#pragma unroll
    for (int o = 16; o; o >>= 1) s += __shfl_xor_sync(0xffffffffu, s, o);
    __syncthreads();
    if ((tid & 31) == 0) sm[tid >> 5] = s;
    __syncthreads();
    if (tid < 32) {
        float v = (tid < 8) ? sm[tid] : 0.f;
#pragma unroll
        for (int o = 4; o; o >>= 1) v += __shfl_xor_sync(0xffffffffu, v, o);
        if (tid == 0) bval = v;
    }
    __syncthreads();
    const float inv = 1.f / bval;

    for (int k = tid; k <= q; k += 256) {
        float v = pe[k] * inv;
        __nv_bfloat16 hv = __float2bfloat16(v);
        ph[k] = hv;
        pl[k] = __float2bfloat16(v - __bfloat162float(hv));
    }
    const __nv_bfloat16 z = __float2bfloat16(0.f);
    for (int k = q + 1 + tid; k < S_; k += 256) { ph[k] = z; pl[k] = z; }
}

// ============================================================================
// Host launcher — graph-capturable: kernel launches only, no sync, no alloc.
// ============================================================================
extern "C" void kernel_launch(void* const* d_in, const int* in_sizes, int n_in,
                              void* d_out, int out_size)
{
    const float* x  = (const float*)d_in[0];   // [B,S,DIN]
    const float* Wq = (const float*)d_in[1];   // [DIN,DK]
    const float* Wk = (const float*)d_in[2];   // [DIN,DK]
    const float* Wv = (const float*)d_in[3];   // [DIN,DV]
    float* out = (float*)d_out;                // [B,S,DV]

    __nv_bfloat16 *xh, *xl, *Wqth, *Wqtl, *Wkth, *Wktl;
    __nv_bfloat16 *Qh, *Ql, *Kh, *Kl, *Vth, *Vtl, *Ph, *Pl;
    float *Vp, *Pp;
    cudaGetSymbolAddress((void**)&xh, g_xh);
    cudaGetSymbolAddress((void**)&xl, g_xl);
    cudaGetSymbolAddress((void**)&Wqth, g_Wqt_h);
    cudaGetSymbolAddress((void**)&Wqtl, g_Wqt_l);
    cudaGetSymbolAddress((void**)&Wkth, g_Wkt_h);
    cudaGetSymbolAddress((void**)&Wktl, g_Wkt_l);
    cudaGetSymbolAddress((void**)&Qh, g_Qh);
    cudaGetSymbolAddress((void**)&Ql, g_Ql);
    cudaGetSymbolAddress((void**)&Kh, g_Kh);
    cudaGetSymbolAddress((void**)&Kl, g_Kl);
    cudaGetSymbolAddress((void**)&Vp, g_V);
    cudaGetSymbolAddress((void**)&Vth, g_Vt_h);
    cudaGetSymbolAddress((void**)&Vtl, g_Vt_l);
    cudaGetSymbolAddress((void**)&Pp, g_P);
    cudaGetSymbolAddress((void**)&Ph, g_Ph);
    cudaGetSymbolAddress((void**)&Pl, g_Pl);

    const dim3 blk(256);
    const float scale = 1.0f / sqrtf((float)DK);

    // 1) split x into bf16 hi/lo
    split_kernel<<<(MTOT * DIN + 255) / 256, blk>>>(x, xh, xl, MTOT * DIN);

    // 2) split+transpose Wq, Wk: [DIN,DK] -> [DK,DIN]
    split_transpose<<<dim3(DK / 32, DIN / 32, 1), dim3(32, 8)>>>(
        Wq, Wqth, Wqtl, DIN, DK, 0, 0);
    split_transpose<<<dim3(DK / 32, DIN / 32, 1), dim3(32, 8)>>>(
        Wk, Wkth, Wktl, DIN, DK, 0, 0);

    // 3) Q = x@Wq, K = x@Wk on tensor cores, epilogue writes bf16 hi/lo
    gemm_bf16split_nt<<<dim3(DK / 128, MTOT / 128, 1), blk>>>(
        xh, xl, Wqth, Wqtl, nullptr, Qh, Ql,
        MTOT, DK, DIN, DIN, DIN, DK, 0, 0, 0, 1.0f, 1, 0);
    gemm_bf16split_nt<<<dim3(DK / 128, MTOT / 128, 1), blk>>>(
        xh, xl, Wkth, Wktl, nullptr, Kh, Kl,
        MTOT, DK, DIN, DIN, DIN, DK, 0, 0, 0, 1.0f, 1, 0);

    // 4) V = x@Wv (tiny, fp32 SIMT), then split+transpose per batch
    sgemm_nn<<<dim3(1, MTOT / 128, 1), blk>>>(x, Wv, Vp, MTOT, DV, DIN,
                                              DIN, DV, DV);
    split_transpose<<<dim3(DV / 32, S_ / 32, B_), dim3(32, 8)>>>(
        Vp, Vth, Vtl, S_, DV, (long)S_ * DV, (long)DV * S_);

    // 5) scores = scale * Q@K^T (causal tile skip), fp32 out
    gemm_bf16split_nt<<<dim3(S_ / 128, S_ / 128, B_), blk>>>(
        Qh, Ql, Kh, Kl, Pp, nullptr, nullptr,
        S_, S_, DK, DK, DK, S_,
        (long)S_ * DK, (long)S_ * DK, (long)S_ * S_, scale, 0, 1);

    // 6) softmax -> bf16 hi/lo probs (masked half zero-filled)
    softmax_causal<<<dim3(B_ * S_), blk>>>(Pp, Ph, Pl, Pp);

    // 7) O = P@V (K capped at diagonal), fp32 out
    gemm_bf16split_nt<<<dim3(1, S_ / 128, B_), blk>>>(
        Ph, Pl, Vth, Vtl, out, nullptr, nullptr,
        S_, DV, S_, S_, S_, DV,
        (long)S_ * S_, (long)DV * S_, (long)S_ * DV, 1.0f, 0, 2);
}

// round 8
// speedup vs baseline: 4.0310x; 1.1833x over previous
#include <cuda_runtime.h>
#include <cuda_bf16.h>
#include <math.h>
#include <stdint.h>

// Problem constants
#define B_    4
#define S_    2048
#define DIN   512
#define DK    2048
#define DV    64
#define MTOT  (B_*S_)        // 8192

typedef __nv_bfloat16 bf16;

// ---------------- scratch (static device globals: allocation-free) ----------
__device__ bf16 g_xh[(size_t)MTOT * DIN];
__device__ bf16 g_xl[(size_t)MTOT * DIN];
__device__ bf16 g_Wqt_h[(size_t)DK * DIN];   // [N=DK][K=DIN]
__device__ bf16 g_Wqt_l[(size_t)DK * DIN];
__device__ bf16 g_Wkt_h[(size_t)DK * DIN];
__device__ bf16 g_Wkt_l[(size_t)DK * DIN];
__device__ bf16 g_Qh[(size_t)MTOT * DK];
__device__ bf16 g_Ql[(size_t)MTOT * DK];
__device__ bf16 g_Kh[(size_t)MTOT * DK];
__device__ bf16 g_Kl[(size_t)MTOT * DK];
__device__ float g_V [(size_t)MTOT * DV];
__device__ bf16 g_Vt_h[(size_t)B_ * DV * S_];  // [b][DV][S]
__device__ bf16 g_Vt_l[(size_t)B_ * DV * S_];
__device__ float g_P [(size_t)B_ * S_ * S_];   // fp32 scores
__device__ bf16 g_Ph[(size_t)B_ * S_ * S_];
__device__ bf16 g_Pl[(size_t)B_ * S_ * S_];

// ---------------------------------------------------------------------------
// PTX helpers
// ---------------------------------------------------------------------------
__device__ __forceinline__ void ldsm_x4(uint32_t* r, uint32_t addr) {
    asm volatile("ldmatrix.sync.aligned.m8n8.x4.shared.b16 {%0,%1,%2,%3}, [%4];\n"
                 : "=r"(r[0]), "=r"(r[1]), "=r"(r[2]), "=r"(r[3]) : "r"(addr));
}
__device__ __forceinline__ void mma_bf16(float* c, const uint32_t* a,
                                         uint32_t b0, uint32_t b1) {
    asm volatile("mma.sync.aligned.m16n8k16.row.col.f32.bf16.bf16.f32 "
                 "{%0,%1,%2,%3}, {%4,%5,%6,%7}, {%8,%9}, {%0,%1,%2,%3};\n"
                 : "+f"(c[0]), "+f"(c[1]), "+f"(c[2]), "+f"(c[3])
                 : "r"(a[0]), "r"(a[1]), "r"(a[2]), "r"(a[3]), "r"(b0), "r"(b1));
}
__device__ __forceinline__ void cp16(uint32_t dst, const void* src) {
    asm volatile("cp.async.cg.shared.global [%0], [%1], 16;\n"
                 :: "r"(dst), "l"(src));
}
#define CP_COMMIT() asm volatile("cp.async.commit_group;\n" ::: "memory")
#define CP_WAIT(n)  asm volatile("cp.async.wait_group %0;\n" :: "n"(n) : "memory")

__device__ __forceinline__ uint32_t smem_u32(const void* p) {
    uint32_t a;
    asm("{ .reg .u64 t; cvta.to.shared.u64 t, %1; cvt.u32.u64 %0, t; }"
        : "=r"(a) : "l"(p));
    return a;
}

// ---------------------------------------------------------------------------
// cp.async 3-stage pipelined split-bf16 NT GEMM on mma.sync:
//   C[M,N] = (Ah+Al)[M,K] * (Bh+Bl)[N,K]^T    (drops Al*Bl)
// BM=128 fixed. Template: BN (CTA n-tile), WM/WN (warp tile), WGN (warp grid n).
// 256 threads = 8 warps = (8/WGN) x WGN grid of WM x WN tiles.
// K consumed in 32-chunks; smem rows padded to 40 bf16 (80B, LDSM conflict-free).
// mode 0: fp32 alpha*C.  mode 1: bf16 hi/lo split output.
// causal 1: skip tiles fully above diagonal.  causal 2: K capped at m0+128.
// ---------------------------------------------------------------------------
template<int BN, int WM, int WN, int WGN>
__global__ __launch_bounds__(256)
void gemm_cp(const bf16* __restrict__ Ah_g, const bf16* __restrict__ Al_g,
             const bf16* __restrict__ Bh_g, const bf16* __restrict__ Bl_g,
             float* __restrict__ Cf, bf16* __restrict__ Ch, bf16* __restrict__ Cl,
             int M, int N, int K, int lda, int ldb, int ldc,
             long sA, long sB, long sC, float alpha, int mode, int causal)
{
    constexpr int BM   = 128;
    constexpr int MT   = WM / 16;       // m16 tiles per warp
    constexpr int PN   = WN / 16;       // n16 (ldsm) tiles per warp
    constexpr int ROWB = 80;            // bytes per smem row (40 bf16)
    constexpr int A_B  = BM * ROWB;     // one A operand tile (hi or lo)
    constexpr int Bt_B = BN * ROWB;
    constexpr int STAGE = 2 * A_B + 2 * Bt_B;

    extern __shared__ char smem[];
    const uint32_t sb = smem_u32(smem);

    const int m0 = blockIdx.y * BM;
    const int n0 = blockIdx.x * BN;
    if (causal == 1 && n0 > m0 + BM - 1) return;

    const int bz = blockIdx.z;
    Ah_g += (size_t)bz * sA;  Al_g += (size_t)bz * sA;
    Bh_g += (size_t)bz * sB;  Bl_g += (size_t)bz * sB;

    int Keff = K;
    if (causal == 2) Keff = (m0 + BM < K) ? (m0 + BM) : K;
    const int nCh = Keff >> 5;

    const int tid  = threadIdx.x;
    const int lane = tid & 31;
    const int wid  = tid >> 5;
    const int wm   = wid / WGN;
    const int wn   = wid % WGN;

    float acc[MT][WN / 8][4];
#pragma unroll
    for (int i = 0; i < MT; i++)
#pragma unroll
        for (int j = 0; j < WN / 8; j++)
#pragma unroll
            for (int q = 0; q < 4; q++) acc[i][j][q] = 0.f;

    // ---- async stage loader: chunk c -> stage slot st ----
    auto load_stage = [&](int c, int st) {
        const int kt = c << 5;
        const uint32_t s = sb + st * STAGE;
#pragma unroll
        for (int v = tid; v < BM * 4; v += 256) {
            const int r = v >> 2, cc = v & 3;
            const size_t go = (size_t)(m0 + r) * lda + kt + cc * 8;
            cp16(s + r * ROWB + cc * 16, Ah_g + go);
            cp16(s + A_B + r * ROWB + cc * 16, Al_g + go);
        }
#pragma unroll
        for (int v = tid; v < BN * 4; v += 256) {
            const int r = v >> 2, cc = v & 3;
            const size_t go = (size_t)(n0 + r) * ldb + kt + cc * 8;
            cp16(s + 2 * A_B + r * ROWB + cc * 16, Bh_g + go);
            cp16(s + 2 * A_B + Bt_B + r * ROWB + cc * 16, Bl_g + go);
        }
    };

    // prologue: stages 0, 1
    load_stage(0, 0);
    CP_COMMIT();
    if (nCh > 1) load_stage(1, 1);
    CP_COMMIT();

    for (int c = 0; c < nCh; c++) {
        CP_WAIT(1);
        __syncthreads();
        if (c + 2 < nCh) load_stage(c + 2, (c + 2) % 3);
        CP_COMMIT();

        // ---- compute chunk c from stage c%3 ----
        const uint32_t s  = sb + (c % 3) * STAGE;
        const uint32_t uA = s, uAl = s + A_B;
        const uint32_t uB = s + 2 * A_B, uBl = s + 2 * A_B + Bt_B;
#pragma unroll
        for (int ks = 0; ks < 32; ks += 16) {
            uint32_t ah[MT][4], al[MT][4];
            const int ar = wm * WM + (lane & 15);
            const int ac = (ks + ((lane >> 4) << 3)) * 2;
#pragma unroll
            for (int mt = 0; mt < MT; mt++) {
                ldsm_x4(ah[mt], uA  + (uint32_t)(ar + mt * 16) * ROWB + ac);
                ldsm_x4(al[mt], uAl + (uint32_t)(ar + mt * 16) * ROWB + ac);
            }
            const int br = wn * WN + (lane & 7) + ((lane >> 4) << 3);
            const int bc = (ks + (((lane >> 3) & 1) << 3)) * 2;
#pragma unroll
            for (int p = 0; p < PN; p++) {
                uint32_t bh[4], bl[4];
                ldsm_x4(bh, uB  + (uint32_t)(br + 16 * p) * ROWB + bc);
                ldsm_x4(bl, uBl + (uint32_t)(br + 16 * p) * ROWB + bc);
#pragma unroll
                for (int mt = 0; mt < MT; mt++) {
                    mma_bf16(acc[mt][2 * p],     ah[mt], bh[0], bh[1]);
                    mma_bf16(acc[mt][2 * p],     ah[mt], bl[0], bl[1]);
                    mma_bf16(acc[mt][2 * p],     al[mt], bh[0], bh[1]);
                    mma_bf16(acc[mt][2 * p + 1], ah[mt], bh[2], bh[3]);
                    mma_bf16(acc[mt][2 * p + 1], ah[mt], bl[2], bl[3]);
                    mma_bf16(acc[mt][2 * p + 1], al[mt], bh[2], bh[3]);
                }
            }
        }
        __syncthreads();
    }
    CP_WAIT(0);

    // ---- epilogue: acc regs -> global (vectorized pairs) ----
    const int r  = lane >> 2;
    const int cl = (lane & 3) * 2;
#pragma unroll
    for (int mt = 0; mt < MT; mt++) {
#pragma unroll
        for (int nt = 0; nt < WN / 8; nt++) {
            const int gm = m0 + wm * WM + mt * 16 + r;
            const int gn = n0 + wn * WN + nt * 8 + cl;
            const float* a = acc[mt][nt];
            if (mode == 0) {
                float* Cb = Cf + (size_t)bz * sC;
                *(float2*)(Cb + (size_t)gm * ldc + gn) =
                    make_float2(a[0] * alpha, a[1] * alpha);
                *(float2*)(Cb + (size_t)(gm + 8) * ldc + gn) =
                    make_float2(a[2] * alpha, a[3] * alpha);
            } else {
#pragma unroll
                for (int half = 0; half < 2; half++) {
                    const int mm = gm + half * 8;
                    const float v0 = a[half * 2], v1 = a[half * 2 + 1];
                    const bf16 h0 = __float2bfloat16(v0);
                    const bf16 h1 = __float2bfloat16(v1);
                    const bf16 l0 = __float2bfloat16(v0 - __bfloat162float(h0));
                    const bf16 l1 = __float2bfloat16(v1 - __bfloat162float(h1));
                    *(__nv_bfloat162*)(Ch + (size_t)mm * ldc + gn) =
                        __nv_bfloat162(h0, h1);
                    *(__nv_bfloat162*)(Cl + (size_t)mm * ldc + gn) =
                        __nv_bfloat162(l0, l1);
                }
            }
        }
    }
}

// smem sizes per template config
#define STAGE_MAIN (2 * 128 * 80 + 2 * 256 * 80)   // 61440
#define SMEM_MAIN  (3 * STAGE_MAIN)                // 184320
#define STAGE_PV   (2 * 128 * 80 + 2 * 64 * 80)    // 30720
#define SMEM_PV    (3 * STAGE_PV)                  // 92160

// ---------------------------------------------------------------------------
// Elementwise split: fp32 -> (hi bf16, lo bf16)
// ---------------------------------------------------------------------------
__global__ __launch_bounds__(256)
void split_kernel(const float* __restrict__ src, bf16* __restrict__ h,
                  bf16* __restrict__ l, int n)
{
    int i = blockIdx.x * 256 + threadIdx.x;
    if (i < n) {
        float v = src[i];
        bf16 hv = __float2bfloat16(v);
        h[i] = hv;
        l[i] = __float2bfloat16(v - __bfloat162float(hv));
    }
}

// ---------------------------------------------------------------------------
// Split + transpose: src fp32 [R,C] -> dst hi/lo bf16 [C,R]. Batched.
// ---------------------------------------------------------------------------
__global__ __launch_bounds__(256)
void split_transpose(const float* __restrict__ src, bf16* __restrict__ dh,
                     bf16* __restrict__ dl, int R, int C, long sSrc, long sDst)
{
    __shared__ float t[32][33];
    const int b = blockIdx.z;
    src += (size_t)b * sSrc;
    dh  += (size_t)b * sDst;
    dl  += (size_t)b * sDst;
    const int c0 = blockIdx.x * 32;
    const int r0 = blockIdx.y * 32;
    const int x = threadIdx.x, y = threadIdx.y;
#pragma unroll
    for (int i = 0; i < 32; i += 8)
        t[y + i][x] = src[(size_t)(r0 + y + i) * C + c0 + x];
    __syncthreads();
#pragma unroll
    for (int i = 0; i < 32; i += 8) {
        float v = t[x][y + i];
        bf16 hv = __float2bfloat16(v);
        size_t o = (size_t)(c0 + y + i) * R + r0 + x;
        dh[o] = hv;
        dl[o] = __float2bfloat16(v - __bfloat162float(hv));
    }
}

// ============================================================================
// fp32 SIMT SGEMM (tiny V projection only: N=64, K=512)
// ============================================================================
__global__ __launch_bounds__(256)
void sgemm_nn(const float* __restrict__ A, const float* __restrict__ Bm,
              float* __restrict__ C, int M, int N, int K, int lda, int ldb, int ldc)
{
    __shared__ __align__(16) float As[8][128];
    __shared__ __align__(16) float Bs[8][128];

    const int m0 = blockIdx.y * 128;
    const int n0 = blockIdx.x * 128;
    const int tid = threadIdx.x;
    const int tx = tid & 15, ty = tid >> 4;
    const int arow = tid >> 1, acol = (tid & 1) * 4;
    const int brow = tid >> 5, bcol = (tid & 31) * 4;
    const bool bok = (n0 + bcol) < N;

    float acc[8][8];
#pragma unroll
    for (int i = 0; i < 8; i++)
#pragma unroll
        for (int j = 0; j < 8; j++) acc[i][j] = 0.f;

    for (int kt = 0; kt < K; kt += 8) {
        float4 av = *(const float4*)(A + (size_t)(m0 + arow) * lda + kt + acol);
        As[acol + 0][arow] = av.x; As[acol + 1][arow] = av.y;
        As[acol + 2][arow] = av.z; As[acol + 3][arow] = av.w;
        float4 bv = make_float4(0.f, 0.f, 0.f, 0.f);
        if (bok) bv = *(const float4*)(Bm + (size_t)(kt + brow) * ldb + n0 + bcol);
        *(float4*)&Bs[brow][bcol] = bv;
        __syncthreads();
#pragma unroll
        for (int k = 0; k < 8; k++) {
            float4 a0 = *(const float4*)&As[k][ty * 8];
            float4 a1 = *(const float4*)&As[k][ty * 8 + 4];
            float4 b0 = *(const float4*)&Bs[k][tx * 8];
            float4 b1 = *(const float4*)&Bs[k][tx * 8 + 4];
            float a[8] = {a0.x, a0.y, a0.z, a0.w, a1.x, a1.y, a1.z, a1.w};
            float b[8] = {b0.x, b0.y, b0.z, b0.w, b1.x, b1.y, b1.z, b1.w};
#pragma unroll
            for (int i = 0; i < 8; i++)
#pragma unroll
                for (int j = 0; j < 8; j++)
                    acc[i][j] = fmaf(a[i], b[j], acc[i][j]);
        }
        __syncthreads();
    }
#pragma unroll
    for (int i = 0; i < 8; i++) {
        const int m = m0 + ty * 8 + i;
        const int n = n0 + tx * 8;
        if (n < N)
            *(float4*)(C + (size_t)m * ldc + n) =
                make_float4(acc[i][0], acc[i][1], acc[i][2], acc[i][3]);
        if (n + 4 < N)
            *(float4*)(C + (size_t)m * ldc + n + 4) =
                make_float4(acc[i][4], acc[i][5], acc[i][6], acc[i][7]);
    }
}

// ============================================================================
// Causal row softmax: fp32 scores -> bf16 hi/lo probs; zero-fills k > q.
// ============================================================================
__global__ __launch_bounds__(256)
void softmax_causal(const float* __restrict__ P, bf16* __restrict__ Ph,
                    bf16* __restrict__ Pl, float* __restrict__ Pexp)
{
    const int row = blockIdx.x;
    const int q = row & (S_ - 1);
    const float* p = P + (size_t)row * S_;
    float* pe = Pexp + (size_t)row * S_;
    bf16* ph = Ph + (size_t)row * S_;
    bf16* pl = Pl + (size_t)row * S_;
    const int tid = threadIdx.x;

    __shared__ float sm[8];
    __shared__ float bval;

    float mx = -INFINITY;
    for (int k = tid; k <= q; k += 256) mx = fmaxf(mx, p[k]);
#pragma unroll
    for (int o = 16; o; o >>= 1) mx = fmaxf(mx, __shfl_xor_sync(0xffffffffu, mx, o));
    if ((tid & 31) == 0) sm[tid >> 5] = mx;
    __syncthreads();
    if (tid < 32) {
        float v = (tid < 8) ? sm[tid] : -INFINITY;
#pragma unroll
        for (int o = 4; o; o >>= 1) v = fmaxf(v, __shfl_xor_sync(0xffffffffu, v, o));
        if (tid == 0) bval = v;
    }
    __syncthreads();
    mx = bval;

    float s = 0.f;
    for (int k = tid; k <= q; k += 256) {
        float e = expf(p[k] - mx);
        pe[k] = e;
        s += e;
    }
#pragma unroll
    for (int o = 16; o; o >>= 1) s += __shfl_xor_sync(0xffffffffu, s, o);
    __syncthreads();
    if ((tid & 31) == 0) sm[tid >> 5] = s;
    __syncthreads();
    if (tid < 32) {
        float v = (tid < 8) ? sm[tid] : 0.f;
#pragma unroll
        for (int o = 4; o; o >>= 1) v += __shfl_xor_sync(0xffffffffu, v, o);
        if (tid == 0) bval = v;
    }
    __syncthreads();
    const float inv = 1.f / bval;

    for (int k = tid; k <= q; k += 256) {
        float v = pe[k] * inv;
        bf16 hv = __float2bfloat16(v);
        ph[k] = hv;
        pl[k] = __float2bfloat16(v - __bfloat162float(hv));
    }
    const bf16 z = __float2bfloat16(0.f);
    for (int k = q + 1 + tid; k < S_; k += 256) { ph[k] = z; pl[k] = z; }
}

// ============================================================================
// Host launcher — graph-capturable: kernel launches only, no sync, no alloc.
// ============================================================================
extern "C" void kernel_launch(void* const* d_in, const int* in_sizes, int n_in,
                              void* d_out, int out_size)
{
    const float* x  = (const float*)d_in[0];
    const float* Wq = (const float*)d_in[1];
    const float* Wk = (const float*)d_in[2];
    const float* Wv = (const float*)d_in[3];
    float* out = (float*)d_out;

    bf16 *xh, *xl, *Wqth, *Wqtl, *Wkth, *Wktl;
    bf16 *Qh, *Ql, *Kh, *Kl, *Vth, *Vtl, *Ph, *Pl;
    float *Vp, *Pp;
    cudaGetSymbolAddress((void**)&xh, g_xh);
    cudaGetSymbolAddress((void**)&xl, g_xl);
    cudaGetSymbolAddress((void**)&Wqth, g_Wqt_h);
    cudaGetSymbolAddress((void**)&Wqtl, g_Wqt_l);
    cudaGetSymbolAddress((void**)&Wkth, g_Wkt_h);
    cudaGetSymbolAddress((void**)&Wktl, g_Wkt_l);
    cudaGetSymbolAddress((void**)&Qh, g_Qh);
    cudaGetSymbolAddress((void**)&Ql, g_Ql);
    cudaGetSymbolAddress((void**)&Kh, g_Kh);
    cudaGetSymbolAddress((void**)&Kl, g_Kl);
    cudaGetSymbolAddress((void**)&Vp, g_V);
    cudaGetSymbolAddress((void**)&Vth, g_Vt_h);
    cudaGetSymbolAddress((void**)&Vtl, g_Vt_l);
    cudaGetSymbolAddress((void**)&Pp, g_P);
    cudaGetSymbolAddress((void**)&Ph, g_Ph);
    cudaGetSymbolAddress((void**)&Pl, g_Pl);

    // idempotent (no static guards): raise dynamic smem limits every call
    cudaFuncSetAttribute(gemm_cp<256, 64, 64, 4>,
                         cudaFuncAttributeMaxDynamicSharedMemorySize, SMEM_MAIN);
    cudaFuncSetAttribute(gemm_cp<64, 32, 32, 2>,
                         cudaFuncAttributeMaxDynamicSharedMemorySize, SMEM_PV);

    const dim3 blk(256);
    const float scale = 1.0f / sqrtf((float)DK);

    // 1) split x into bf16 hi/lo
    split_kernel<<<(MTOT * DIN + 255) / 256, blk>>>(x, xh, xl, MTOT * DIN);

    // 2) split+transpose Wq, Wk: [DIN,DK] -> [DK,DIN]
    split_transpose<<<dim3(DK / 32, DIN / 32, 1), dim3(32, 8)>>>(
        Wq, Wqth, Wqtl, DIN, DK, 0, 0);
    split_transpose<<<dim3(DK / 32, DIN / 32, 1), dim3(32, 8)>>>(
        Wk, Wkth, Wktl, DIN, DK, 0, 0);

    // 3) Q/K projections (tensor cores, split bf16 out)
    gemm_cp<256, 64, 64, 4><<<dim3(DK / 256, MTOT / 128, 1), blk, SMEM_MAIN>>>(
        xh, xl, Wqth, Wqtl, nullptr, Qh, Ql,
        MTOT, DK, DIN, DIN, DIN, DK, 0, 0, 0, 1.0f, 1, 0);
    gemm_cp<256, 64, 64, 4><<<dim3(DK / 256, MTOT / 128, 1), blk, SMEM_MAIN>>>(
        xh, xl, Wkth, Wktl, nullptr, Kh, Kl,
        MTOT, DK, DIN, DIN, DIN, DK, 0, 0, 0, 1.0f, 1, 0);

    // 4) V = x@Wv (fp32 SIMT), split+transpose per batch -> [DV, S]
    sgemm_nn<<<dim3(1, MTOT / 128, 1), blk>>>(x, Wv, Vp, MTOT, DV, DIN,
                                              DIN, DV, DV);
    split_transpose<<<dim3(DV / 32, S_ / 32, B_), dim3(32, 8)>>>(
        Vp, Vth, Vtl, S_, DV, (long)S_ * DV, (long)DV * S_);

    // 5) scores = scale * Q@K^T (causal tile skip), fp32 out
    gemm_cp<256, 64, 64, 4><<<dim3(S_ / 256, S_ / 128, B_), blk, SMEM_MAIN>>>(
        Qh, Ql, Kh, Kl, Pp, nullptr, nullptr,
        S_, S_, DK, DK, DK, S_,
        (long)S_ * DK, (long)S_ * DK, (long)S_ * S_, scale, 0, 1);

    // 6) softmax -> bf16 hi/lo probs (masked half zero-filled)
    softmax_causal<<<dim3(B_ * S_), blk>>>(Pp, Ph, Pl, Pp);

    // 7) O = P@V (K capped at diagonal), fp32 out
    gemm_cp<64, 32, 32, 2><<<dim3(1, S_ / 128, B_), blk, SMEM_PV>>>(
        Ph, Pl, Vth, Vtl, out, nullptr, nullptr,
        S_, DV, S_, S_, S_, DV,
        (long)S_ * S_, (long)DV * S_, (long)S_ * DV, 1.0f, 0, 2);
}

// round 9
// speedup vs baseline: 4.5479x; 1.1282x over previous
#include <cuda_runtime.h>
#include <cuda_bf16.h>
#include <math.h>
#include <stdint.h>

// Problem constants
#define B_    4
#define S_    2048
#define DIN   512
#define DK    2048
#define DV    64
#define MTOT  (B_*S_)        // 8192
#define NSPLIT 4             // split-K factor for P*V

typedef __nv_bfloat16 bf16;

// ---------------- scratch (static device globals: allocation-free) ----------
__device__ bf16 g_xh[(size_t)MTOT * DIN];
__device__ bf16 g_xl[(size_t)MTOT * DIN];
__device__ bf16 g_Wqkt_h[(size_t)2 * DK * DIN];  // [2*DK][DIN] (Wq^T ; Wk^T)
__device__ bf16 g_Wqkt_l[(size_t)2 * DK * DIN];
__device__ bf16 g_QKh[(size_t)MTOT * 2 * DK];    // [B*S][4096] (Q ; K)
__device__ bf16 g_QKl[(size_t)MTOT * 2 * DK];
__device__ float g_V [(size_t)MTOT * DV];
__device__ bf16 g_Vt_h[(size_t)B_ * DV * S_];    // [b][DV][S]
__device__ bf16 g_Vt_l[(size_t)B_ * DV * S_];
__device__ float g_P [(size_t)B_ * S_ * S_];     // fp32 scores
__device__ bf16 g_Ph[(size_t)B_ * S_ * S_];
__device__ bf16 g_Pl[(size_t)B_ * S_ * S_];
__device__ float g_Opart[(size_t)NSPLIT * B_ * S_ * DV];  // P*V partials

// ---------------------------------------------------------------------------
// PTX helpers
// ---------------------------------------------------------------------------
__device__ __forceinline__ void ldsm_x4(uint32_t* r, uint32_t addr) {
    asm volatile("ldmatrix.sync.aligned.m8n8.x4.shared.b16 {%0,%1,%2,%3}, [%4];\n"
                 : "=r"(r[0]), "=r"(r[1]), "=r"(r[2]), "=r"(r[3]) : "r"(addr));
}
__device__ __forceinline__ void mma_bf16(float* c, const uint32_t* a,
                                         uint32_t b0, uint32_t b1) {
    asm volatile("mma.sync.aligned.m16n8k16.row.col.f32.bf16.bf16.f32 "
                 "{%0,%1,%2,%3}, {%4,%5,%6,%7}, {%8,%9}, {%0,%1,%2,%3};\n"
                 : "+f"(c[0]), "+f"(c[1]), "+f"(c[2]), "+f"(c[3])
                 : "r"(a[0]), "r"(a[1]), "r"(a[2]), "r"(a[3]), "r"(b0), "r"(b1));
}
__device__ __forceinline__ void cp16(uint32_t dst, const void* src) {
    asm volatile("cp.async.cg.shared.global [%0], [%1], 16;\n"
                 :: "r"(dst), "l"(src));
}
#define CP_COMMIT() asm volatile("cp.async.commit_group;\n" ::: "memory")
#define CP_WAIT(n)  asm volatile("cp.async.wait_group %0;\n" :: "n"(n) : "memory")

__device__ __forceinline__ uint32_t smem_u32(const void* p) {
    uint32_t a;
    asm("{ .reg .u64 t; cvta.to.shared.u64 t, %1; cvt.u32.u64 %0, t; }"
        : "=r"(a) : "l"(p));
    return a;
}

// ---------------------------------------------------------------------------
// cp.async 2-stage pipelined split-bf16 NT GEMM on mma.sync:
//   C[M,N] = (Ah+Al)[M,K] * (Bh+Bl)[N,K]^T    (drops Al*Bl)
// BM=128. Template: BN (CTA n-tile), WM/WN (warp tile), WGN (warp grid n).
// 256 threads = 8 warps, min 2 CTAs/SM (regs capped at 128 for occupancy).
// K consumed in 32-chunks; smem rows padded to 40 bf16 (80B, LDSM conflict-free).
// mode 0: fp32 alpha*C.  mode 1: bf16 hi/lo split output.
// causal 1: skip tiles fully above diagonal.  causal 2: K capped at m0+128.
// kslices > 1: grid.z = batches*kslices; slice s computes K range
//   [s*K/kslices, ...) and writes into Cf + s*sSplit (split-K partials).
// ---------------------------------------------------------------------------
template<int BN, int WM, int WN, int WGN>
__global__ __launch_bounds__(256, 2)
void gemm_cp(const bf16* __restrict__ Ah_g, const bf16* __restrict__ Al_g,
             const bf16* __restrict__ Bh_g, const bf16* __restrict__ Bl_g,
             float* __restrict__ Cf, bf16* __restrict__ Ch, bf16* __restrict__ Cl,
             int M, int N, int K, int lda, int ldb, int ldc,
             long sA, long sB, long sC, float alpha, int mode, int causal,
             int kslices, long sSplit)
{
    constexpr int BM   = 128;
    constexpr int MT   = WM / 16;       // m16 tiles per warp
    constexpr int PN   = WN / 16;       // n16 (ldsm) tiles per warp
    constexpr int ROWB = 80;            // bytes per smem row (40 bf16)
    constexpr int A_B  = BM * ROWB;     // one A operand tile (hi or lo)
    constexpr int Bt_B = BN * ROWB;
    constexpr int STAGE = 2 * A_B + 2 * Bt_B;

    extern __shared__ char smem[];
    const uint32_t sb = smem_u32(smem);

    const int m0 = blockIdx.y * BM;
    const int n0 = blockIdx.x * BN;
    if (causal == 1 && n0 > m0 + BM - 1) return;

    int bz = blockIdx.z, sidx = 0;
    if (kslices > 1) { sidx = bz % kslices; bz /= kslices; }
    Ah_g += (size_t)bz * sA;  Al_g += (size_t)bz * sA;
    Bh_g += (size_t)bz * sB;  Bl_g += (size_t)bz * sB;

    int Kcap = K;
    if (causal == 2) Kcap = (m0 + BM < K) ? (m0 + BM) : K;
    int kbeg = 0, kend = Kcap;
    if (kslices > 1) {
        const int ksp = K / kslices;
        kbeg = sidx * ksp;
        kend = (kbeg + ksp < Kcap) ? (kbeg + ksp) : Kcap;
        if (kbeg >= kend) return;
    }
    const int c0 = kbeg >> 5, c1 = kend >> 5;
    const int nCh = c1 - c0;

    const int tid  = threadIdx.x;
    const int lane = tid & 31;
    const int wid  = tid >> 5;
    const int wm   = wid / WGN;
    const int wn   = wid % WGN;

    float acc[MT][WN / 8][4];
#pragma unroll
    for (int i = 0; i < MT; i++)
#pragma unroll
        for (int j = 0; j < WN / 8; j++)
#pragma unroll
            for (int q = 0; q < 4; q++) acc[i][j][q] = 0.f;

    // ---- async stage loader: chunk c -> stage slot st ----
    auto load_stage = [&](int c, int st) {
        const int kt = c << 5;
        const uint32_t s = sb + st * STAGE;
#pragma unroll
        for (int v = tid; v < BM * 4; v += 256) {
            const int r = v >> 2, cc = v & 3;
            const size_t go = (size_t)(m0 + r) * lda + kt + cc * 8;
            cp16(s + r * ROWB + cc * 16, Ah_g + go);
            cp16(s + A_B + r * ROWB + cc * 16, Al_g + go);
        }
#pragma unroll
        for (int v = tid; v < BN * 4; v += 256) {
            const int r = v >> 2, cc = v & 3;
            const size_t go = (size_t)(n0 + r) * ldb + kt + cc * 8;
            cp16(s + 2 * A_B + r * ROWB + cc * 16, Bh_g + go);
            cp16(s + 2 * A_B + Bt_B + r * ROWB + cc * 16, Bl_g + go);
        }
    };

    // prologue: fill both stages
    load_stage(c0, 0);
    CP_COMMIT();
    if (nCh > 1) load_stage(c0 + 1, 1);
    CP_COMMIT();

    for (int c = c0; c < c1; c++) {
        CP_WAIT(1);
        __syncthreads();

        // ---- compute chunk c from stage (c-c0)&1 ----
        const uint32_t s  = sb + ((c - c0) & 1) * STAGE;
        const uint32_t uA = s, uAl = s + A_B;
        const uint32_t uB = s + 2 * A_B, uBl = s + 2 * A_B + Bt_B;
#pragma unroll
        for (int ks = 0; ks < 32; ks += 16) {
            uint32_t ah[MT][4], al[MT][4];
            const int ar = wm * WM + (lane & 15);
            const int ac = (ks + ((lane >> 4) << 3)) * 2;
#pragma unroll
            for (int mt = 0; mt < MT; mt++) {
                ldsm_x4(ah[mt], uA  + (uint32_t)(ar + mt * 16) * ROWB + ac);
                ldsm_x4(al[mt], uAl + (uint32_t)(ar + mt * 16) * ROWB + ac);
            }
            const int br = wn * WN + (lane & 7) + ((lane >> 4) << 3);
            const int bc = (ks + (((lane >> 3) & 1) << 3)) * 2;
#pragma unroll
            for (int p = 0; p < PN; p++) {
                uint32_t bh[4], bl[4];
                ldsm_x4(bh, uB  + (uint32_t)(br + 16 * p) * ROWB + bc);
                ldsm_x4(bl, uBl + (uint32_t)(br + 16 * p) * ROWB + bc);
#pragma unroll
                for (int mt = 0; mt < MT; mt++) {
                    mma_bf16(acc[mt][2 * p],     ah[mt], bh[0], bh[1]);
                    mma_bf16(acc[mt][2 * p],     ah[mt], bl[0], bl[1]);
                    mma_bf16(acc[mt][2 * p],     al[mt], bh[0], bh[1]);
                    mma_bf16(acc[mt][2 * p + 1], ah[mt], bh[2], bh[3]);
                    mma_bf16(acc[mt][2 * p + 1], ah[mt], bl[2], bl[3]);
                    mma_bf16(acc[mt][2 * p + 1], al[mt], bh[2], bh[3]);
                }
            }
        }
        __syncthreads();                 // stage (c-c0)&1 fully consumed
        if (c + 2 < c1) load_stage(c + 2, (c - c0) & 1);
        CP_COMMIT();
    }
    CP_WAIT(0);

    // ---- epilogue: acc regs -> global (vectorized pairs) ----
    const int r  = lane >> 2;
    const int cl = (lane & 3) * 2;
#pragma unroll
    for (int mt = 0; mt < MT; mt++) {
#pragma unroll
        for (int nt = 0; nt < WN / 8; nt++) {
            const int gm = m0 + wm * WM + mt * 16 + r;
            const int gn = n0 + wn * WN + nt * 8 + cl;
            const float* a = acc[mt][nt];
            if (mode == 0) {
                float* Cb = Cf + (size_t)sidx * sSplit + (size_t)bz * sC;
                *(float2*)(Cb + (size_t)gm * ldc + gn) =
                    make_float2(a[0] * alpha, a[1] * alpha);
                *(float2*)(Cb + (size_t)(gm + 8) * ldc + gn) =
                    make_float2(a[2] * alpha, a[3] * alpha);
            } else {
#pragma unroll
                for (int half = 0; half < 2; half++) {
                    const int mm = gm + half * 8;
                    const float v0 = a[half * 2], v1 = a[half * 2 + 1];
                    const bf16 h0 = __float2bfloat16(v0);
                    const bf16 h1 = __float2bfloat16(v1);
                    const bf16 l0 = __float2bfloat16(v0 - __bfloat162float(h0));
                    const bf16 l1 = __float2bfloat16(v1 - __bfloat162float(h1));
                    *(__nv_bfloat162*)(Ch + (size_t)mm * ldc + gn) =
                        __nv_bfloat162(h0, h1);
                    *(__nv_bfloat162*)(Cl + (size_t)mm * ldc + gn) =
                        __nv_bfloat162(l0, l1);
                }
            }
        }
    }
}

// smem stage sizes
#define SMEM_MAIN (2 * (2 * 128 * 80 + 2 * 128 * 80))   // 81920
#define SMEM_PV   (2 * (2 * 128 * 80 + 2 * 64 * 80))    // 61440

// ---------------------------------------------------------------------------
// P*V split-K reduction: out[b,m,:] = sum over active slices of partials.
// Slice s is active for row m iff s*(S/NSPLIT) < m0+128, i.e. s <= m>>9.
// ---------------------------------------------------------------------------
__global__ __launch_bounds__(256)
void pv_reduce(const float* __restrict__ part, float* __restrict__ out)
{
    const int idx = blockIdx.x * 256 + threadIdx.x;
    if (idx >= B_ * S_ * DV) return;
    const int m = (idx / DV) & (S_ - 1);
    const int ns = (m >> 9) + 1;        // 1..4 active slices
    float v = 0.f;
#pragma unroll
    for (int s = 0; s < NSPLIT; s++)
        if (s < ns) v += part[(size_t)s * (B_ * S_ * DV) + idx];
    out[idx] = v;
}

// ---------------------------------------------------------------------------
// Elementwise split: fp32 -> (hi bf16, lo bf16)
// ---------------------------------------------------------------------------
__global__ __launch_bounds__(256)
void split_kernel(const float* __restrict__ src, bf16* __restrict__ h,
                  bf16* __restrict__ l, int n)
{
    int i = blockIdx.x * 256 + threadIdx.x;
    if (i < n) {
        float v = src[i];
        bf16 hv = __float2bfloat16(v);
        h[i] = hv;
        l[i] = __float2bfloat16(v - __bfloat162float(hv));
    }
}

// ---------------------------------------------------------------------------
// Split + transpose: src fp32 [R,C] -> dst hi/lo bf16 [C,R]. Batched.
// ---------------------------------------------------------------------------
__global__ __launch_bounds__(256)
void split_transpose(const float* __restrict__ src, bf16* __restrict__ dh,
                     bf16* __restrict__ dl, int R, int C, long sSrc, long sDst)
{
    __shared__ float t[32][33];
    const int b = blockIdx.z;
    src += (size_t)b * sSrc;
    dh  += (size_t)b * sDst;
    dl  += (size_t)b * sDst;
    const int c0 = blockIdx.x * 32;
    const int r0 = blockIdx.y * 32;
    const int x = threadIdx.x, y = threadIdx.y;
#pragma unroll
    for (int i = 0; i < 32; i += 8)
        t[y + i][x] = src[(size_t)(r0 + y + i) * C + c0 + x];
    __syncthreads();
#pragma unroll
    for (int i = 0; i < 32; i += 8) {
        float v = t[x][y + i];
        bf16 hv = __float2bfloat16(v);
        size_t o = (size_t)(c0 + y + i) * R + r0 + x;
        dh[o] = hv;
        dl[o] = __float2bfloat16(v - __bfloat162float(hv));
    }
}

// ============================================================================
// fp32 SIMT SGEMM (tiny V projection only: N=64, K=512)
// ============================================================================
__global__ __launch_bounds__(256)
void sgemm_nn(const float* __restrict__ A, const float* __restrict__ Bm,
              float* __restrict__ C, int M, int N, int K, int lda, int ldb, int ldc)
{
    __shared__ __align__(16) float As[8][128];
    __shared__ __align__(16) float Bs[8][128];

    const int m0 = blockIdx.y * 128;
    const int n0 = blockIdx.x * 128;
    const int tid = threadIdx.x;
    const int tx = tid & 15, ty = tid >> 4;
    const int arow = tid >> 1, acol = (tid & 1) * 4;
    const int brow = tid >> 5, bcol = (tid & 31) * 4;
    const bool bok = (n0 + bcol) < N;

    float acc[8][8];
#pragma unroll
    for (int i = 0; i < 8; i++)
#pragma unroll
        for (int j = 0; j < 8; j++) acc[i][j] = 0.f;

    for (int kt = 0; kt < K; kt += 8) {
        float4 av = *(const float4*)(A + (size_t)(m0 + arow) * lda + kt + acol);
        As[acol + 0][arow] = av.x; As[acol + 1][arow] = av.y;
        As[acol + 2][arow] = av.z; As[acol + 3][arow] = av.w;
        float4 bv = make_float4(0.f, 0.f, 0.f, 0.f);
        if (bok) bv = *(const float4*)(Bm + (size_t)(kt + brow) * ldb + n0 + bcol);
        *(float4*)&Bs[brow][bcol] = bv;
        __syncthreads();
#pragma unroll
        for (int k = 0; k < 8; k++) {
            float4 a0 = *(const float4*)&As[k][ty * 8];
            float4 a1 = *(const float4*)&As[k][ty * 8 + 4];
            float4 b0 = *(const float4*)&Bs[k][tx * 8];
            float4 b1 = *(const float4*)&Bs[k][tx * 8 + 4];
            float a[8] = {a0.x, a0.y, a0.z, a0.w, a1.x, a1.y, a1.z, a1.w};
            float b[8] = {b0.x, b0.y, b0.z, b0.w, b1.x, b1.y, b1.z, b1.w};
#pragma unroll
            for (int i = 0; i < 8; i++)
#pragma unroll
                for (int j = 0; j < 8; j++)
                    acc[i][j] = fmaf(a[i], b[j], acc[i][j]);
        }
        __syncthreads();
    }
#pragma unroll
    for (int i = 0; i < 8; i++) {
        const int m = m0 + ty * 8 + i;
        const int n = n0 + tx * 8;
        if (n < N)
            *(float4*)(C + (size_t)m * ldc + n) =
                make_float4(acc[i][0], acc[i][1], acc[i][2], acc[i][3]);
        if (n + 4 < N)
            *(float4*)(C + (size_t)m * ldc + n + 4) =
                make_float4(acc[i][4], acc[i][5], acc[i][6], acc[i][7]);
    }
}

// ============================================================================
// Causal row softmax: fp32 scores -> bf16 hi/lo probs; zero-fills k > q.
// ============================================================================
__global__ __launch_bounds__(256)
void softmax_causal(const float* __restrict__ P, bf16* __restrict__ Ph,
                    bf16* __restrict__ Pl, float* __restrict__ Pexp)
{
    const int row = blockIdx.x;
    const int q = row & (S_ - 1);
    const float* p = P + (size_t)row * S_;
    float* pe = Pexp + (size_t)row * S_;
    bf16* ph = Ph + (size_t)row * S_;
    bf16* pl = Pl + (size_t)row * S_;
    const int tid = threadIdx.x;

    __shared__ float sm[8];
    __shared__ float bval;

    float mx = -INFINITY;
    for (int k = tid; k <= q; k += 256) mx = fmaxf(mx, p[k]);
#pragma unroll
    for (int o = 16; o; o >>= 1) mx = fmaxf(mx, __shfl_xor_sync(0xffffffffu, mx, o));
    if ((tid & 31) == 0) sm[tid >> 5] = mx;
    __syncthreads();
    if (tid < 32) {
        float v = (tid < 8) ? sm[tid] : -INFINITY;
#pragma unroll
        for (int o = 4; o; o >>= 1) v = fmaxf(v, __shfl_xor_sync(0xffffffffu, v, o));
        if (tid == 0) bval = v;
    }
    __syncthreads();
    mx = bval;

    float s = 0.f;
    for (int k = tid; k <= q; k += 256) {
        float e = expf(p[k] - mx);
        pe[k] = e;
        s += e;
    }
#pragma unroll
    for (int o = 16; o; o >>= 1) s += __shfl_xor_sync(0xffffffffu, s, o);
    __syncthreads();
    if ((tid & 31) == 0) sm[tid >> 5] = s;
    __syncthreads();
    if (tid < 32) {
        float v = (tid < 8) ? sm[tid] : 0.f;
#pragma unroll
        for (int o = 4; o; o >>= 1) v += __shfl_xor_sync(0xffffffffu, v, o);
        if (tid == 0) bval = v;
    }
    __syncthreads();
    const float inv = 1.f / bval;

    for (int k = tid; k <= q; k += 256) {
        float v = pe[k] * inv;
        bf16 hv = __float2bfloat16(v);
        ph[k] = hv;
        pl[k] = __float2bfloat16(v - __bfloat162float(hv));
    }
    const bf16 z = __float2bfloat16(0.f);
    for (int k = q + 1 + tid; k < S_; k += 256) { ph[k] = z; pl[k] = z; }
}

// ============================================================================
// Host launcher — graph-capturable: kernel launches only, no sync, no alloc.
// ============================================================================
extern "C" void kernel_launch(void* const* d_in, const int* in_sizes, int n_in,
                              void* d_out, int out_size)
{
    const float* x  = (const float*)d_in[0];
    const float* Wq = (const float*)d_in[1];
    const float* Wk = (const float*)d_in[2];
    const float* Wv = (const float*)d_in[3];
    float* out = (float*)d_out;

    bf16 *xh, *xl, *Wqkth, *Wqktl, *QKh, *QKl, *Vth, *Vtl, *Ph, *Pl;
    float *Vp, *Pp, *Opart;
    cudaGetSymbolAddress((void**)&xh, g_xh);
    cudaGetSymbolAddress((void**)&xl, g_xl);
    cudaGetSymbolAddress((void**)&Wqkth, g_Wqkt_h);
    cudaGetSymbolAddress((void**)&Wqktl, g_Wqkt_l);
    cudaGetSymbolAddress((void**)&QKh, g_QKh);
    cudaGetSymbolAddress((void**)&QKl, g_QKl);
    cudaGetSymbolAddress((void**)&Vp, g_V);
    cudaGetSymbolAddress((void**)&Vth, g_Vt_h);
    cudaGetSymbolAddress((void**)&Vtl, g_Vt_l);
    cudaGetSymbolAddress((void**)&Pp, g_P);
    cudaGetSymbolAddress((void**)&Ph, g_Ph);
    cudaGetSymbolAddress((void**)&Pl, g_Pl);
    cudaGetSymbolAddress((void**)&Opart, g_Opart);

    // idempotent: raise dynamic smem limits every call
    cudaFuncSetAttribute(gemm_cp<128, 32, 64, 2>,
                         cudaFuncAttributeMaxDynamicSharedMemorySize, SMEM_MAIN);
    cudaFuncSetAttribute(gemm_cp<64, 32, 32, 2>,
                         cudaFuncAttributeMaxDynamicSharedMemorySize, SMEM_PV);

    const dim3 blk(256);
    const float scale = 1.0f / sqrtf((float)DK);

    // 1) split x into bf16 hi/lo
    split_kernel<<<(MTOT * DIN + 255) / 256, blk>>>(x, xh, xl, MTOT * DIN);

    // 2) split+transpose Wq, Wk into combined [2*DK][DIN]
    split_transpose<<<dim3(DK / 32, DIN / 32, 1), dim3(32, 8)>>>(
        Wq, Wqkth, Wqktl, DIN, DK, 0, 0);
    split_transpose<<<dim3(DK / 32, DIN / 32, 1), dim3(32, 8)>>>(
        Wk, Wqkth + (size_t)DK * DIN, Wqktl + (size_t)DK * DIN, DIN, DK, 0, 0);

    // 3) fused Q+K projection: [MTOT, 4096] = x @ [Wq ; Wk]
    gemm_cp<128, 32, 64, 2><<<dim3(2 * DK / 128, MTOT / 128, 1), blk, SMEM_MAIN>>>(
        xh, xl, Wqkth, Wqktl, nullptr, QKh, QKl,
        MTOT, 2 * DK, DIN, DIN, DIN, 2 * DK, 0, 0, 0, 1.0f, 1, 0, 1, 0);

    // 4) V = x@Wv (fp32 SIMT), split+transpose per batch -> [DV, S]
    sgemm_nn<<<dim3(1, MTOT / 128, 1), blk>>>(x, Wv, Vp, MTOT, DV, DIN,
                                              DIN, DV, DV);
    split_transpose<<<dim3(DV / 32, S_ / 32, B_), dim3(32, 8)>>>(
        Vp, Vth, Vtl, S_, DV, (long)S_ * DV, (long)DV * S_);

    // 5) scores = scale * Q@K^T (causal tile skip), fp32 out
    gemm_cp<128, 32, 64, 2><<<dim3(S_ / 128, S_ / 128, B_), blk, SMEM_MAIN>>>(
        QKh, QKl, QKh + DK, QKl + DK, Pp, nullptr, nullptr,
        S_, S_, DK, 2 * DK, 2 * DK, S_,
        (long)S_ * 2 * DK, (long)S_ * 2 * DK, (long)S_ * S_, scale, 0, 1, 1, 0);

    // 6) softmax -> bf16 hi/lo probs (masked half zero-filled)
    softmax_causal<<<dim3(B_ * S_), blk>>>(Pp, Ph, Pl, Pp);

    // 7) O_partial = P@V with split-K x4 (K capped at diagonal per row-block)
    gemm_cp<64, 32, 32, 2><<<dim3(1, S_ / 128, B_ * NSPLIT), blk, SMEM_PV>>>(
        Ph, Pl, Vth, Vtl, Opart, nullptr, nullptr,
        S_, DV, S_, S_, S_, DV,
        (long)S_ * S_, (long)DV * S_, (long)S_ * DV, 1.0f, 0, 2,
        NSPLIT, (long)B_ * S_ * DV);

    // 8) reduce partials -> out
    pv_reduce<<<(B_ * S_ * DV + 255) / 256, blk>>>(Opart, out);
}

// round 11
// speedup vs baseline: 5.2297x; 1.1499x over previous
#include <cuda_runtime.h>
#include <cuda_bf16.h>
#include <math.h>
#include <stdint.h>

// Problem constants
#define B_    4
#define S_    2048
#define DIN   512
#define DK    2048
#define DV    64
#define MTOT  (B_*S_)        // 8192
#define NSPLIT 4             // split-K factor for P*V

typedef __nv_bfloat16 bf16;

// ---------------- scratch (static device globals: allocation-free) ----------
__device__ bf16 g_xh[(size_t)MTOT * DIN];
__device__ bf16 g_xl[(size_t)MTOT * DIN];
__device__ bf16 g_Wqkt_h[(size_t)2 * DK * DIN];  // [2*DK][DIN] (Wq^T ; Wk^T)
__device__ bf16 g_Wqkt_l[(size_t)2 * DK * DIN];
__device__ bf16 g_Wvt_h[(size_t)128 * DIN];      // [64 used + 64 zero pad][DIN]
__device__ bf16 g_Wvt_l[(size_t)128 * DIN];
__device__ bf16 g_QKh[(size_t)MTOT * 2 * DK];    // [B*S][4096] (Q ; K)
__device__ bf16 g_QKl[(size_t)MTOT * 2 * DK];
__device__ bf16 g_Vt_h[(size_t)DV * MTOT];       // [DV][B*S]  (V^T, batch in cols)
__device__ bf16 g_Vt_l[(size_t)DV * MTOT];
__device__ float g_P [(size_t)B_ * S_ * S_];     // fp32 scores
__device__ bf16 g_Ph[(size_t)B_ * S_ * S_];      // unnormalized exp, hi/lo
__device__ bf16 g_Pl[(size_t)B_ * S_ * S_];
__device__ float g_sums[(size_t)B_ * S_];        // softmax row sums
__device__ float g_Opart[(size_t)NSPLIT * B_ * S_ * DV];  // P*V partials

// ---------------------------------------------------------------------------
// PTX helpers
// ---------------------------------------------------------------------------
__device__ __forceinline__ void ldsm_x4(uint32_t* r, uint32_t addr) {
    asm volatile("ldmatrix.sync.aligned.m8n8.x4.shared.b16 {%0,%1,%2,%3}, [%4];\n"
                 : "=r"(r[0]), "=r"(r[1]), "=r"(r[2]), "=r"(r[3]) : "r"(addr));
}
__device__ __forceinline__ void mma_bf16(float* c, const uint32_t* a,
                                         uint32_t b0, uint32_t b1) {
    asm volatile("mma.sync.aligned.m16n8k16.row.col.f32.bf16.bf16.f32 "
                 "{%0,%1,%2,%3}, {%4,%5,%6,%7}, {%8,%9}, {%0,%1,%2,%3};\n"
                 : "+f"(c[0]), "+f"(c[1]), "+f"(c[2]), "+f"(c[3])
                 : "r"(a[0]), "r"(a[1]), "r"(a[2]), "r"(a[3]), "r"(b0), "r"(b1));
}
__device__ __forceinline__ void cp16(uint32_t dst, const void* src) {
    asm volatile("cp.async.cg.shared.global [%0], [%1], 16;\n"
                 :: "r"(dst), "l"(src));
}
#define CP_COMMIT() asm volatile("cp.async.commit_group;\n" ::: "memory")
#define CP_WAIT(n)  asm volatile("cp.async.wait_group %0;\n" :: "n"(n) : "memory")

__device__ __forceinline__ uint32_t smem_u32(const void* p) {
    uint32_t a;
    asm("{ .reg .u64 t; cvta.to.shared.u64 t, %1; cvt.u32.u64 %0, t; }"
        : "=r"(a) : "l"(p));
    return a;
}

// ---------------------------------------------------------------------------
// cp.async 2-stage pipelined split-bf16 NT GEMM on mma.sync (ONE barrier/chunk):
//   C[M,N] = (Ah+Al)[M,K] * (Bh+Bl)[N,K]^T    (drops Al*Bl)
// BM=128. Template: BN (CTA n-tile), WM/WN (warp tile), WGN (warp grid n).
// 256 threads = 8 warps, 2 CTAs/SM. K in 32-chunks; smem rows 40 bf16 (80B).
// mode 0: fp32 alpha*C.  mode 1: bf16 hi/lo split output.
// causal 1: skip tiles fully above diagonal.  causal 2: K capped at m0+128.
// kslices > 1: grid.z = batches*kslices; slice s covers K range s*K/kslices..
//   and writes into Cf + s*sSplit (split-K partials).
// Epilogue rows guarded by gm < M (allows M < BM with padded A).
// ---------------------------------------------------------------------------
template<int BN, int WM, int WN, int WGN>
__global__ __launch_bounds__(256, 2)
void gemm_cp(const bf16* __restrict__ Ah_g, const bf16* __restrict__ Al_g,
             const bf16* __restrict__ Bh_g, const bf16* __restrict__ Bl_g,
             float* __restrict__ Cf, bf16* __restrict__ Ch, bf16* __restrict__ Cl,
             int M, int N, int K, int lda, int ldb, int ldc,
             long sA, long sB, long sC, float alpha, int mode, int causal,
             int kslices, long sSplit)
{
    constexpr int BM   = 128;
    constexpr int MT   = WM / 16;
    constexpr int PN   = WN / 16;
    constexpr int ROWB = 80;
    constexpr int A_B  = BM * ROWB;
    constexpr int Bt_B = BN * ROWB;
    constexpr int STAGE = 2 * A_B + 2 * Bt_B;

    extern __shared__ char smem[];
    const uint32_t sb = smem_u32(smem);

    const int m0 = blockIdx.y * BM;
    const int n0 = blockIdx.x * BN;
    if (causal == 1 && n0 > m0 + BM - 1) return;

    int bz = blockIdx.z, sidx = 0;
    if (kslices > 1) { sidx = bz % kslices; bz /= kslices; }
    Ah_g += (size_t)bz * sA;  Al_g += (size_t)bz * sA;
    Bh_g += (size_t)bz * sB;  Bl_g += (size_t)bz * sB;

    int Kcap = K;
    if (causal == 2) Kcap = (m0 + BM < K) ? (m0 + BM) : K;
    int kbeg = 0, kend = Kcap;
    if (kslices > 1) {
        const int ksp = K / kslices;
        kbeg = sidx * ksp;
        kend = (kbeg + ksp < Kcap) ? (kbeg + ksp) : Kcap;
        if (kbeg >= kend) return;
    }
    const int c0 = kbeg >> 5, c1 = kend >> 5;

    const int tid  = threadIdx.x;
    const int lane = tid & 31;
    const int wid  = tid >> 5;
    const int wm   = wid / WGN;
    const int wn   = wid % WGN;

    float acc[MT][WN / 8][4];
#pragma unroll
    for (int i = 0; i < MT; i++)
#pragma unroll
        for (int j = 0; j < WN / 8; j++)
#pragma unroll
            for (int q = 0; q < 4; q++) acc[i][j][q] = 0.f;

    auto load_stage = [&](int c, int st) {
        const int kt = c << 5;
        const uint32_t s = sb + st * STAGE;
#pragma unroll
        for (int v = tid; v < BM * 4; v += 256) {
            const int r = v >> 2, cc = v & 3;
            const size_t go = (size_t)(m0 + r) * lda + kt + cc * 8;
            cp16(s + r * ROWB + cc * 16, Ah_g + go);
            cp16(s + A_B + r * ROWB + cc * 16, Al_g + go);
        }
#pragma unroll
        for (int v = tid; v < BN * 4; v += 256) {
            const int r = v >> 2, cc = v & 3;
            const size_t go = (size_t)(n0 + r) * ldb + kt + cc * 8;
            cp16(s + 2 * A_B + r * ROWB + cc * 16, Bh_g + go);
            cp16(s + 2 * A_B + Bt_B + r * ROWB + cc * 16, Bl_g + go);
        }
    };

    load_stage(c0, 0);
    CP_COMMIT();

    for (int c = c0; c < c1; c++) {
        CP_WAIT(0);
        __syncthreads();     // stage (c-c0)&1 visible; prior compute on other stage done
        if (c + 1 < c1) {
            load_stage(c + 1, (c - c0 + 1) & 1);
            CP_COMMIT();
        }

        const uint32_t s  = sb + ((c - c0) & 1) * STAGE;
        const uint32_t uA = s, uAl = s + A_B;
        const uint32_t uB = s + 2 * A_B, uBl = s + 2 * A_B + Bt_B;
#pragma unroll
        for (int ks = 0; ks < 32; ks += 16) {
            uint32_t ah[MT][4], al[MT][4];
            const int ar = wm * WM + (lane & 15);
            const int ac = (ks + ((lane >> 4) << 3)) * 2;
#pragma unroll
            for (int mt = 0; mt < MT; mt++) {
                ldsm_x4(ah[mt], uA  + (uint32_t)(ar + mt * 16) * ROWB + ac);
                ldsm_x4(al[mt], uAl + (uint32_t)(ar + mt * 16) * ROWB + ac);
            }
            const int br = wn * WN + (lane & 7) + ((lane >> 4) << 3);
            const int bc = (ks + (((lane >> 3) & 1) << 3)) * 2;
#pragma unroll
            for (int p = 0; p < PN; p++) {
                uint32_t bh[4], bl[4];
                ldsm_x4(bh, uB  + (uint32_t)(br + 16 * p) * ROWB + bc);
                ldsm_x4(bl, uBl + (uint32_t)(br + 16 * p) * ROWB + bc);
#pragma unroll
                for (int mt = 0; mt < MT; mt++) {
                    mma_bf16(acc[mt][2 * p],     ah[mt], bh[0], bh[1]);
                    mma_bf16(acc[mt][2 * p],     ah[mt], bl[0], bl[1]);
                    mma_bf16(acc[mt][2 * p],     al[mt], bh[0], bh[1]);
                    mma_bf16(acc[mt][2 * p + 1], ah[mt], bh[2], bh[3]);
                    mma_bf16(acc[mt][2 * p + 1], ah[mt], bl[2], bl[3]);
                    mma_bf16(acc[mt][2 * p + 1], al[mt], bh[2], bh[3]);
                }
            }
        }
    }

    // ---- epilogue ----
    const int r  = lane >> 2;
    const int cl = (lane & 3) * 2;
#pragma unroll
    for (int mt = 0; mt < MT; mt++) {
#pragma unroll
        for (int nt = 0; nt < WN / 8; nt++) {
            const int gm = m0 + wm * WM + mt * 16 + r;
            const int gn = n0 + wn * WN + nt * 8 + cl;
            const float* a = acc[mt][nt];
            if (mode == 0) {
                float* Cb = Cf + (size_t)sidx * sSplit + (size_t)bz * sC;
                if (gm < M)
                    *(float2*)(Cb + (size_t)gm * ldc + gn) =
                        make_float2(a[0] * alpha, a[1] * alpha);
                if (gm + 8 < M)
                    *(float2*)(Cb + (size_t)(gm + 8) * ldc + gn) =
                        make_float2(a[2] * alpha, a[3] * alpha);
            } else {
#pragma unroll
                for (int half = 0; half < 2; half++) {
                    const int mm = gm + half * 8;
                    if (mm >= M) continue;
                    const float v0 = a[half * 2], v1 = a[half * 2 + 1];
                    const bf16 h0 = __float2bfloat16(v0);
                    const bf16 h1 = __float2bfloat16(v1);
                    const bf16 l0 = __float2bfloat16(v0 - __bfloat162float(h0));
                    const bf16 l1 = __float2bfloat16(v1 - __bfloat162float(h1));
                    *(__nv_bfloat162*)(Ch + (size_t)mm * ldc + gn) =
                        __nv_bfloat162(h0, h1);
                    *(__nv_bfloat162*)(Cl + (size_t)mm * ldc + gn) =
                        __nv_bfloat162(l0, l1);
                }
            }
        }
    }
}

// smem stage sizes
#define SMEM_MAIN (2 * (2 * 128 * 80 + 2 * 128 * 80))   // 81920
#define SMEM_PV   (2 * (2 * 128 * 80 + 2 * 64 * 80))    // 61440

// ---------------------------------------------------------------------------
// P*V split-K reduction + deferred softmax normalization:
//   out[b,m,:] = (sum over active slices of partials) / rowsum[b,m]
// ---------------------------------------------------------------------------
__global__ __launch_bounds__(256)
void pv_reduce(const float* __restrict__ part, const float* __restrict__ sums,
               float* __restrict__ out)
{
    const int idx = blockIdx.x * 256 + threadIdx.x;
    if (idx >= B_ * S_ * DV) return;
    const int row = idx / DV;            // b*S + m
    const int m = row & (S_ - 1);
    const int ns = (m >> 9) + 1;         // 1..4 active slices
    float v = 0.f;
#pragma unroll
    for (int s = 0; s < NSPLIT; s++)
        if (s < ns) v += part[(size_t)s * (B_ * S_ * DV) + idx];
    out[idx] = v / sums[row];
}

// ---------------------------------------------------------------------------
// Elementwise split: fp32 -> (hi bf16, lo bf16)
// ---------------------------------------------------------------------------
__global__ __launch_bounds__(256)
void split_kernel(const float* __restrict__ src, bf16* __restrict__ h,
                  bf16* __restrict__ l, int n)
{
    int i = blockIdx.x * 256 + threadIdx.x;
    if (i < n) {
        float v = src[i];
        bf16 hv = __float2bfloat16(v);
        h[i] = hv;
        l[i] = __float2bfloat16(v - __bfloat162float(hv));
    }
}

// ---------------------------------------------------------------------------
// Split + transpose: src fp32 [R,C] -> dst hi/lo bf16 [C,R]. Batched.
// ---------------------------------------------------------------------------
__global__ __launch_bounds__(256)
void split_transpose(const float* __restrict__ src, bf16* __restrict__ dh,
                     bf16* __restrict__ dl, int R, int C, long sSrc, long sDst)
{
    __shared__ float t[32][33];
    const int b = blockIdx.z;
    src += (size_t)b * sSrc;
    dh  += (size_t)b * sDst;
    dl  += (size_t)b * sDst;
    const int c0 = blockIdx.x * 32;
    const int r0 = blockIdx.y * 32;
    const int x = threadIdx.x, y = threadIdx.y;
#pragma unroll
    for (int i = 0; i < 32; i += 8)
        t[y + i][x] = src[(size_t)(r0 + y + i) * C + c0 + x];
    __syncthreads();
#pragma unroll
    for (int i = 0; i < 32; i += 8) {
        float v = t[x][y + i];
        bf16 hv = __float2bfloat16(v);
        size_t o = (size_t)(c0 + y + i) * R + r0 + x;
        dh[o] = hv;
        dl[o] = __float2bfloat16(v - __bfloat162float(hv));
    }
}

// ============================================================================
// Causal row softmax, 2-pass: fp32 scores -> UNNORMALIZED exp as bf16 hi/lo,
// row sum to g_sums (normalization deferred to pv_reduce). Zero-fills k > q.
// ============================================================================
__global__ __launch_bounds__(256)
void softmax_causal(const float* __restrict__ P, bf16* __restrict__ Ph,
                    bf16* __restrict__ Pl, float* __restrict__ sums)
{
    const int row = blockIdx.x;
    const int q = row & (S_ - 1);
    const float* p = P + (size_t)row * S_;
    bf16* ph = Ph + (size_t)row * S_;
    bf16* pl = Pl + (size_t)row * S_;
    const int tid = threadIdx.x;

    __shared__ float sm[8];
    __shared__ float bval;

    // pass 1: row max over [0, q]
    float mx = -INFINITY;
    for (int k = tid; k <= q; k += 256) mx = fmaxf(mx, p[k]);
#pragma unroll
    for (int o = 16; o; o >>= 1) mx = fmaxf(mx, __shfl_xor_sync(0xffffffffu, mx, o));
    if ((tid & 31) == 0) sm[tid >> 5] = mx;
    __syncthreads();
    if (tid < 32) {
        float v = (tid < 8) ? sm[tid] : -INFINITY;
#pragma unroll
        for (int o = 4; o; o >>= 1) v = fmaxf(v, __shfl_xor_sync(0xffffffffu, v, o));
        if (tid == 0) bval = v;
    }
    __syncthreads();
    mx = bval;

    // pass 2: e = exp(p - mx) -> split bf16 out; accumulate row sum
    float s = 0.f;
    for (int k = tid; k <= q; k += 256) {
        float e = expf(p[k] - mx);
        s += e;
        bf16 hv = __float2bfloat16(e);
        ph[k] = hv;
        pl[k] = __float2bfloat16(e - __bfloat162float(hv));
    }
#pragma unroll
    for (int o = 16; o; o >>= 1) s += __shfl_xor_sync(0xffffffffu, s, o);
    __syncthreads();
    if ((tid & 31) == 0) sm[tid >> 5] = s;
    __syncthreads();
    if (tid < 32) {
        float v = (tid < 8) ? sm[tid] : 0.f;
#pragma unroll
        for (int o = 4; o; o >>= 1) v += __shfl_xor_sync(0xffffffffu, v, o);
        if (tid == 0) sums[row] = v;
    }

    const bf16 z = __float2bfloat16(0.f);
    for (int k = q + 1 + tid; k < S_; k += 256) { ph[k] = z; pl[k] = z; }
}

// ============================================================================
// Host launcher — graph-capturable: kernel launches only, no sync, no alloc.
// ============================================================================
extern "C" void kernel_launch(void* const* d_in, const int* in_sizes, int n_in,
                              void* d_out, int out_size)
{
    const float* x  = (const float*)d_in[0];
    const float* Wq = (const float*)d_in[1];
    const float* Wk = (const float*)d_in[2];
    const float* Wv = (const float*)d_in[3];
    float* out = (float*)d_out;

    bf16 *xh, *xl, *Wqkth, *Wqktl, *Wvth, *Wvtl, *QKh, *QKl, *Vth, *Vtl, *Ph, *Pl;
    float *Pp, *Opart, *Sums;
    cudaGetSymbolAddress((void**)&xh, g_xh);
    cudaGetSymbolAddress((void**)&xl, g_xl);
    cudaGetSymbolAddress((void**)&Wqkth, g_Wqkt_h);
    cudaGetSymbolAddress((void**)&Wqktl, g_Wqkt_l);
    cudaGetSymbolAddress((void**)&Wvth, g_Wvt_h);
    cudaGetSymbolAddress((void**)&Wvtl, g_Wvt_l);
    cudaGetSymbolAddress((void**)&QKh, g_QKh);
    cudaGetSymbolAddress((void**)&QKl, g_QKl);
    cudaGetSymbolAddress((void**)&Vth, g_Vt_h);
    cudaGetSymbolAddress((void**)&Vtl, g_Vt_l);
    cudaGetSymbolAddress((void**)&Pp, g_P);
    cudaGetSymbolAddress((void**)&Ph, g_Ph);
    cudaGetSymbolAddress((void**)&Pl, g_Pl);
    cudaGetSymbolAddress((void**)&Sums, g_sums);
    cudaGetSymbolAddress((void**)&Opart, g_Opart);

    cudaFuncSetAttribute(gemm_cp<128, 32, 64, 2>,
                         cudaFuncAttributeMaxDynamicSharedMemorySize, SMEM_MAIN);
    cudaFuncSetAttribute(gemm_cp<64, 32, 32, 2>,
                         cudaFuncAttributeMaxDynamicSharedMemorySize, SMEM_PV);

    const dim3 blk(256);
    const float scale = 1.0f / sqrtf((float)DK);

    // 1) split x into bf16 hi/lo
    split_kernel<<<(MTOT * DIN + 255) / 256, blk>>>(x, xh, xl, MTOT * DIN);

    // 2) split+transpose weights: Wq,Wk -> combined [2*DK][DIN]; Wv -> [64][DIN]
    split_transpose<<<dim3(DK / 32, DIN / 32, 1), dim3(32, 8)>>>(
        Wq, Wqkth, Wqktl, DIN, DK, 0, 0);
    split_transpose<<<dim3(DK / 32, DIN / 32, 1), dim3(32, 8)>>>(
        Wk, Wqkth + (size_t)DK * DIN, Wqktl + (size_t)DK * DIN, DIN, DK, 0, 0);
    split_transpose<<<dim3(DV / 32, DIN / 32, 1), dim3(32, 8)>>>(
        Wv, Wvth, Wvtl, DIN, DV, 0, 0);

    // 3) fused Q+K projection: [MTOT, 4096] = x @ [Wq ; Wk]
    gemm_cp<128, 32, 64, 2><<<dim3(2 * DK / 128, MTOT / 128, 1), blk, SMEM_MAIN>>>(
        xh, xl, Wqkth, Wqktl, nullptr, QKh, QKl,
        MTOT, 2 * DK, DIN, DIN, DIN, 2 * DK, 0, 0, 0, 1.0f, 1, 0, 1, 0);

    // 4) V^T = Wv^T @ x^T : C[64, MTOT] (M=64 guarded; A rows 64..127 are zero pad)
    gemm_cp<128, 32, 64, 2><<<dim3(MTOT / 128, 1, 1), blk, SMEM_MAIN>>>(
        Wvth, Wvtl, xh, xl, nullptr, Vth, Vtl,
        DV, MTOT, DIN, DIN, DIN, MTOT, 0, 0, 0, 1.0f, 1, 0, 1, 0);

    // 5) scores = scale * Q@K^T (causal tile skip), fp32 out
    gemm_cp<128, 32, 64, 2><<<dim3(S_ / 128, S_ / 128, B_), blk, SMEM_MAIN>>>(
        QKh, QKl, QKh + DK, QKl + DK, Pp, nullptr, nullptr,
        S_, S_, DK, 2 * DK, 2 * DK, S_,
        (long)S_ * 2 * DK, (long)S_ * 2 * DK, (long)S_ * S_, scale, 0, 1, 1, 0);

    // 6) softmax (2-pass): unnormalized exp -> Ph/Pl, sums -> g_sums
    softmax_causal<<<dim3(B_ * S_), blk>>>(Pp, Ph, Pl, Sums);

    // 7) O_partial = E@V with split-K x4 (V^T in [DV][MTOT], per-batch col offset)
    gemm_cp<64, 32, 32, 2><<<dim3(1, S_ / 128, B_ * NSPLIT), blk, SMEM_PV>>>(
        Ph, Pl, Vth, Vtl, Opart, nullptr, nullptr,
        S_, DV, S_, S_, MTOT, DV,
        (long)S_ * S_, (long)S_, (long)S_ * DV, 1.0f, 0, 2,
        NSPLIT, (long)B_ * S_ * DV);

    // 8) reduce partials, apply 1/rowsum -> out
    pv_reduce<<<(B_ * S_ * DV + 255) / 256, blk>>>(Opart, Sums, out);
}